// round 2
// baseline (speedup 1.0000x reference)
#include <cuda_runtime.h>
#include <math.h>

// ---------------- problem constants ----------------
constexpr int CB   = 4;        // batch
constexpr int CC   = 128;      // channels
constexpr int CT   = 16;
constexpr int CH   = 56;
constexpr int CW   = 56;
constexpr int NHEAD= 4;
constexpr int HD   = 32;
constexpr int NTOK = 196;      // tokens per window (4*7*7)
constexpr int NWIN = 1024;     // B * 4*8*8
constexpr int HID  = 512;
constexpr int MTOK = NWIN * NTOK;     // 200704 total tokens
constexpr int SPT  = CT * CH * CW;    // 50176 spatial per batch
constexpr int HW   = CH * CW;         // 3136

// ---------------- scratch (device globals; no runtime alloc) ----------------
__device__ float g_qkv[(size_t)MTOK * 384];   // window-token-major, [3][NH][HD] cols
__device__ float g_att[(size_t)MTOK * CC];    // attention output (pre-proj), window-token-major
__device__ float g_y1 [(size_t)MTOK * CC];    // after first residual, token-major (b,t,h,w) x C
__device__ float g_hid[(size_t)MTOK * HID];   // mlp hidden

// window-token row R -> (batch, spatial offset)
__device__ __forceinline__ void row_to_bsp(int R, int &b, int &sp) {
    int w = R / NTOK, n = R - w * NTOK;
    b = w >> 8;                    // 256 windows per batch
    int rw = w & 255;
    int it = rw >> 6, ih = (rw >> 3) & 7, iw = rw & 7;
    int tt = n / 49;
    int rn = n - tt * 49;
    int hh = rn / 7, ww = rn - hh * 7;
    sp = (it * 4 + tt) * HW + (ih * 7 + hh) * CW + (iw * 7 + ww);
}

// =====================================================================
// K1: BN + window gather + qkv GEMM  (M=200704, K=128, N=384)
// tile: 64 rows x 64 cols, A resident across 6 col-tiles
// =====================================================================
__global__ __launch_bounds__(256) void k1_qkv(
    const float* __restrict__ x,
    const float* __restrict__ bng, const float* __restrict__ bnb,
    const float* __restrict__ bnm, const float* __restrict__ bnv,
    const float* __restrict__ Wq,  const float* __restrict__ bq)
{
    extern __shared__ float sh[];
    float* As = sh;               // [k=128][r=64], k-major
    float* Bs = sh + 128 * 64;    // [k=128][col=64]
    __shared__ float sc[CC], sf[CC];
    int tid = threadIdx.x;
    if (tid < CC) {
        float s = bng[tid] * rsqrtf(bnv[tid] + 1e-5f);
        sc[tid] = s;
        sf[tid] = bnb[tid] - bnm[tid] * s;
    }
    __syncthreads();

    int r = tid & 63, cseg = tid >> 6;
    int R = blockIdx.x * 64 + r;
    int b, sp; row_to_bsp(R, b, sp);
    int xbase = b * CC * SPT + sp;
    #pragma unroll 8
    for (int i = 0; i < 32; i++) {
        int c = cseg * 32 + i;
        float v = x[xbase + c * SPT];
        As[c * 64 + r] = v * sc[c] + sf[c];
    }

    int ty = tid >> 4, tx = tid & 15;
    for (int nt = 0; nt < 6; nt++) {
        __syncthreads();                      // As ready / Bs consumed
        for (int i = tid; i < 128 * 64; i += 256) {
            int k = i >> 6, col = i & 63;
            Bs[i] = Wq[k * 384 + nt * 64 + col];
        }
        __syncthreads();
        float acc[4][4] = {};
        #pragma unroll 8
        for (int k = 0; k < 128; k++) {
            float4 a  = *(const float4*)&As[k * 64 + ty * 4];
            float4 bv = *(const float4*)&Bs[k * 64 + tx * 4];
            acc[0][0] += a.x*bv.x; acc[0][1] += a.x*bv.y; acc[0][2] += a.x*bv.z; acc[0][3] += a.x*bv.w;
            acc[1][0] += a.y*bv.x; acc[1][1] += a.y*bv.y; acc[1][2] += a.y*bv.z; acc[1][3] += a.y*bv.w;
            acc[2][0] += a.z*bv.x; acc[2][1] += a.z*bv.y; acc[2][2] += a.z*bv.z; acc[2][3] += a.z*bv.w;
            acc[3][0] += a.w*bv.x; acc[3][1] += a.w*bv.y; acc[3][2] += a.w*bv.z; acc[3][3] += a.w*bv.w;
        }
        int col0 = nt * 64 + tx * 4;
        float4 bias = *(const float4*)&bq[col0];
        #pragma unroll
        for (int i = 0; i < 4; i++) {
            int Rr = blockIdx.x * 64 + ty * 4 + i;
            float4 o;
            o.x = acc[i][0] + bias.x; o.y = acc[i][1] + bias.y;
            o.z = acc[i][2] + bias.z; o.w = acc[i][3] + bias.w;
            *(float4*)&g_qkv[Rr * 384 + col0] = o;
        }
    }
}

// =====================================================================
// K2: attention per (window, head).  grid = 4096.
// =====================================================================
__global__ __launch_bounds__(256) void k2_attn()
{
    extern __shared__ float sh[];
    float* Qs = sh;                       // [196][33]
    float* Ks = Qs + NTOK * 33;
    float* Vs = Ks + NTOK * 33;
    float* Ps = Vs + NTOK * 33;           // [8][224] per-warp prob rows
    int w = blockIdx.x >> 2, head = blockIdx.x & 3;
    int tid = threadIdx.x;
    int qbase = w * NTOK;
    int coff = head * 32;

    for (int i = tid; i < NTOK * 32; i += 256) {
        int n = i >> 5, d = i & 31;
        int gi = (qbase + n) * 384 + coff + d;
        Qs[n * 33 + d] = g_qkv[gi];
        Ks[n * 33 + d] = g_qkv[gi + 128];
        Vs[n * 33 + d] = g_qkv[gi + 256];
    }
    __syncthreads();

    int lane = tid & 31, wid = tid >> 5;
    const float scale = 0.17677669529663687f;   // 1/sqrt(32)
    for (int r = wid; r < NTOK; r += 8) {
        float q[32];
        #pragma unroll
        for (int d = 0; d < 32; d++) q[d] = Qs[r * 33 + d];

        float l[7];
        float mx = -1e30f;
        #pragma unroll
        for (int j = 0; j < 7; j++) {
            int m = lane + 32 * j;
            float acc = -1e30f;
            if (m < NTOK) {
                acc = 0.f;
                #pragma unroll
                for (int d = 0; d < 32; d++) acc += q[d] * Ks[m * 33 + d];
                acc *= scale;
            }
            l[j] = acc;
            mx = fmaxf(mx, acc);
        }
        #pragma unroll
        for (int o = 16; o > 0; o >>= 1) mx = fmaxf(mx, __shfl_xor_sync(0xffffffffu, mx, o));
        float se = 0.f;
        #pragma unroll
        for (int j = 0; j < 7; j++) {
            int m = lane + 32 * j;
            if (m < NTOK) { float e = __expf(l[j] - mx); l[j] = e; se += e; }
        }
        #pragma unroll
        for (int o = 16; o > 0; o >>= 1) se += __shfl_xor_sync(0xffffffffu, se, o);
        float inv = 1.f / se;
        #pragma unroll
        for (int j = 0; j < 7; j++) {
            int m = lane + 32 * j;
            if (m < NTOK) Ps[wid * 224 + m] = l[j] * inv;
        }
        __syncwarp();
        float acc = 0.f;
        #pragma unroll 4
        for (int m = 0; m < NTOK; m++) acc += Ps[wid * 224 + m] * Vs[m * 33 + lane];
        g_att[(qbase + r) * 128 + coff + lane] = acc;
        __syncwarp();
    }
}

// =====================================================================
// K3: proj GEMM + window reverse + residual(x) -> y1 (token-major)
// grid = (3136, 2); tile 64x64
// =====================================================================
__global__ __launch_bounds__(256) void k3_proj(
    const float* __restrict__ x,
    const float* __restrict__ Wp, const float* __restrict__ bp)
{
    extern __shared__ float sh[];
    float* As = sh;               // [k=128][r=64], pitch 65
    float* Bs = sh + 128 * 65;    // [k=128][col=64]
    int tid = threadIdx.x;
    int R0 = blockIdx.x * 64;
    for (int i = tid; i < 64 * 128; i += 256) {
        int rl = i >> 7, c = i & 127;
        As[c * 65 + rl] = g_att[(R0 + rl) * 128 + c];
    }
    for (int i = tid; i < 128 * 64; i += 256) {
        int k = i >> 6, col = i & 63;
        Bs[i] = Wp[k * 128 + blockIdx.y * 64 + col];
    }
    __syncthreads();

    int ty = tid >> 4, tx = tid & 15;
    float acc[4][4] = {};
    #pragma unroll 8
    for (int k = 0; k < 128; k++) {
        float a0 = As[k * 65 + ty * 4 + 0];
        float a1 = As[k * 65 + ty * 4 + 1];
        float a2 = As[k * 65 + ty * 4 + 2];
        float a3 = As[k * 65 + ty * 4 + 3];
        float4 bv = *(const float4*)&Bs[k * 64 + tx * 4];
        acc[0][0] += a0*bv.x; acc[0][1] += a0*bv.y; acc[0][2] += a0*bv.z; acc[0][3] += a0*bv.w;
        acc[1][0] += a1*bv.x; acc[1][1] += a1*bv.y; acc[1][2] += a1*bv.z; acc[1][3] += a1*bv.w;
        acc[2][0] += a2*bv.x; acc[2][1] += a2*bv.y; acc[2][2] += a2*bv.z; acc[2][3] += a2*bv.w;
        acc[3][0] += a3*bv.x; acc[3][1] += a3*bv.y; acc[3][2] += a3*bv.z; acc[3][3] += a3*bv.w;
    }
    int col0 = blockIdx.y * 64 + tx * 4;
    float4 bias = *(const float4*)&bp[col0];
    #pragma unroll
    for (int i = 0; i < 4; i++) {
        int Rr = R0 + ty * 4 + i;
        int b, sp; row_to_bsp(Rr, b, sp);
        int xb = b * CC * SPT + sp;
        float4 o;
        o.x = acc[i][0] + bias.x + x[xb + (col0 + 0) * SPT];
        o.y = acc[i][1] + bias.y + x[xb + (col0 + 1) * SPT];
        o.z = acc[i][2] + bias.z + x[xb + (col0 + 2) * SPT];
        o.w = acc[i][3] + bias.w + x[xb + (col0 + 3) * SPT];
        *(float4*)&g_y1[(b * SPT + sp) * 128 + col0] = o;
    }
}

// =====================================================================
// K4a: LN + fc1 + exact GELU -> hidden (M x 512).  grid = 3136.
// =====================================================================
__global__ __launch_bounds__(256) void k4a_ffn1(
    const float* __restrict__ lng, const float* __restrict__ lnb,
    const float* __restrict__ W1,  const float* __restrict__ b1)
{
    extern __shared__ float sh[];
    float* As = sh;               // [k=128][r=64], pitch 65
    float* Bs = sh + 128 * 65;    // [k=128][col=64]
    int tid = threadIdx.x;
    int R0 = blockIdx.x * 64;

    // LN: 4 threads per row, 32 channels each
    int seg = tid & 3, row = tid >> 2;
    const float* src = &g_y1[(R0 + row) * 128 + seg * 32];
    float v[32];
    float s1 = 0.f, s2 = 0.f;
    #pragma unroll
    for (int j = 0; j < 32; j += 4) {
        float4 t = *(const float4*)&src[j];
        v[j] = t.x; v[j+1] = t.y; v[j+2] = t.z; v[j+3] = t.w;
        s1 += t.x + t.y + t.z + t.w;
        s2 += t.x*t.x + t.y*t.y + t.z*t.z + t.w*t.w;
    }
    s1 += __shfl_xor_sync(0xffffffffu, s1, 1);
    s1 += __shfl_xor_sync(0xffffffffu, s1, 2);
    s2 += __shfl_xor_sync(0xffffffffu, s2, 1);
    s2 += __shfl_xor_sync(0xffffffffu, s2, 2);
    float mean = s1 * (1.f / 128.f);
    float var  = s2 * (1.f / 128.f) - mean * mean;
    float rstd = rsqrtf(var + 1e-5f);
    #pragma unroll
    for (int j = 0; j < 32; j++) {
        int c = seg * 32 + j;
        As[c * 65 + row] = (v[j] - mean) * rstd * lng[c] + lnb[c];
    }

    int ty = tid >> 4, tx = tid & 15;
    for (int nt = 0; nt < 8; nt++) {
        __syncthreads();
        for (int i = tid; i < 128 * 64; i += 256) {
            int k = i >> 6, col = i & 63;
            Bs[i] = W1[k * 512 + nt * 64 + col];
        }
        __syncthreads();
        float acc[4][4] = {};
        #pragma unroll 8
        for (int k = 0; k < 128; k++) {
            float a0 = As[k * 65 + ty * 4 + 0];
            float a1 = As[k * 65 + ty * 4 + 1];
            float a2 = As[k * 65 + ty * 4 + 2];
            float a3 = As[k * 65 + ty * 4 + 3];
            float4 bv = *(const float4*)&Bs[k * 64 + tx * 4];
            acc[0][0] += a0*bv.x; acc[0][1] += a0*bv.y; acc[0][2] += a0*bv.z; acc[0][3] += a0*bv.w;
            acc[1][0] += a1*bv.x; acc[1][1] += a1*bv.y; acc[1][2] += a1*bv.z; acc[1][3] += a1*bv.w;
            acc[2][0] += a2*bv.x; acc[2][1] += a2*bv.y; acc[2][2] += a2*bv.z; acc[2][3] += a2*bv.w;
            acc[3][0] += a3*bv.x; acc[3][1] += a3*bv.y; acc[3][2] += a3*bv.z; acc[3][3] += a3*bv.w;
        }
        int col0 = nt * 64 + tx * 4;
        float4 bias = *(const float4*)&b1[col0];
        #pragma unroll
        for (int i = 0; i < 4; i++) {
            int Rr = R0 + ty * 4 + i;
            float h0 = acc[i][0] + bias.x;
            float h1 = acc[i][1] + bias.y;
            float h2 = acc[i][2] + bias.z;
            float h3 = acc[i][3] + bias.w;
            float4 o;
            o.x = 0.5f * h0 * (1.f + erff(h0 * 0.70710678118654752f));
            o.y = 0.5f * h1 * (1.f + erff(h1 * 0.70710678118654752f));
            o.z = 0.5f * h2 * (1.f + erff(h2 * 0.70710678118654752f));
            o.w = 0.5f * h3 * (1.f + erff(h3 * 0.70710678118654752f));
            *(float4*)&g_hid[Rr * 512 + col0] = o;
        }
    }
}

// =====================================================================
// K4b: fc2 + residual(y1) + transposed store to (B,C,T,H,W) output.
// grid = (3136, 2); K=512 in 4 chunks of 128.
// =====================================================================
__global__ __launch_bounds__(256) void k4b_ffn2(
    const float* __restrict__ W2, const float* __restrict__ b2,
    float* __restrict__ out)
{
    extern __shared__ float sh[];
    float* As = sh;               // [k=128][r=64], pitch 65 (reused as Cs)
    float* Bs = sh + 128 * 65;    // [k=128][col=64]
    int tid = threadIdx.x;
    int R0 = blockIdx.x * 64;
    int ty = tid >> 4, tx = tid & 15;
    float acc[4][4] = {};

    for (int kc = 0; kc < 4; kc++) {
        __syncthreads();
        for (int i = tid; i < 64 * 128; i += 256) {
            int rl = i >> 7, kk = i & 127;
            As[kk * 65 + rl] = g_hid[(R0 + rl) * 512 + kc * 128 + kk];
        }
        for (int i = tid; i < 128 * 64; i += 256) {
            int k = i >> 6, col = i & 63;
            Bs[i] = W2[(kc * 128 + k) * 128 + blockIdx.y * 64 + col];
        }
        __syncthreads();
        #pragma unroll 8
        for (int k = 0; k < 128; k++) {
            float a0 = As[k * 65 + ty * 4 + 0];
            float a1 = As[k * 65 + ty * 4 + 1];
            float a2 = As[k * 65 + ty * 4 + 2];
            float a3 = As[k * 65 + ty * 4 + 3];
            float4 bv = *(const float4*)&Bs[k * 64 + tx * 4];
            acc[0][0] += a0*bv.x; acc[0][1] += a0*bv.y; acc[0][2] += a0*bv.z; acc[0][3] += a0*bv.w;
            acc[1][0] += a1*bv.x; acc[1][1] += a1*bv.y; acc[1][2] += a1*bv.z; acc[1][3] += a1*bv.w;
            acc[2][0] += a2*bv.x; acc[2][1] += a2*bv.y; acc[2][2] += a2*bv.z; acc[2][3] += a2*bv.w;
            acc[3][0] += a3*bv.x; acc[3][1] += a3*bv.y; acc[3][2] += a3*bv.z; acc[3][3] += a3*bv.w;
        }
    }

    int col0l = tx * 4;                       // local col 0..63
    int col0g = blockIdx.y * 64 + col0l;
    float4 bias = *(const float4*)&b2[col0g];
    __syncthreads();                           // done with As -> reuse as Cs
    float* Cs = As;                            // [64][65]
    #pragma unroll
    for (int i = 0; i < 4; i++) {
        int Rr = R0 + ty * 4 + i;
        float4 yv = *(const float4*)&g_y1[Rr * 128 + col0g];
        Cs[(ty*4+i) * 65 + col0l + 0] = acc[i][0] + bias.x + yv.x;
        Cs[(ty*4+i) * 65 + col0l + 1] = acc[i][1] + bias.y + yv.y;
        Cs[(ty*4+i) * 65 + col0l + 2] = acc[i][2] + bias.z + yv.z;
        Cs[(ty*4+i) * 65 + col0l + 3] = acc[i][3] + bias.w + yv.w;
    }
    __syncthreads();

    // coalesced transposed store: lanes sweep consecutive tokens
    int colg = tid >> 6, rl = tid & 63;
    int R = R0 + rl;
    int b = R / SPT, sp = R - b * SPT;
    int obase = b * CC * SPT + sp;
    #pragma unroll
    for (int cp = 0; cp < 16; cp++) {
        int col = cp * 4 + colg;
        out[obase + (blockIdx.y * 64 + col) * SPT] = Cs[rl * 65 + col];
    }
}

// =====================================================================
extern "C" void kernel_launch(void* const* d_in, const int* in_sizes, int n_in,
                              void* d_out, int out_size)
{
    const float* x    = (const float*)d_in[0];
    const float* bng  = (const float*)d_in[1];
    const float* bnb  = (const float*)d_in[2];
    const float* bnm  = (const float*)d_in[3];
    const float* bnv  = (const float*)d_in[4];
    const float* qkvw = (const float*)d_in[5];
    const float* qkvb = (const float*)d_in[6];
    const float* pw   = (const float*)d_in[7];
    const float* pb   = (const float*)d_in[8];
    const float* lng  = (const float*)d_in[9];
    const float* lnb  = (const float*)d_in[10];
    const float* w1   = (const float*)d_in[11];
    const float* b1   = (const float*)d_in[12];
    const float* w2   = (const float*)d_in[13];
    const float* b2   = (const float*)d_in[14];
    float* out = (float*)d_out;

    const int smem1 = (128 * 64 + 128 * 64) * 4;                 // 64 KB
    const int smem2 = (3 * NTOK * 33 + 8 * 224) * 4;             // ~84.8 KB
    const int smem3 = (128 * 65 + 128 * 64) * 4;                 // ~66 KB

    cudaFuncSetAttribute(k1_qkv,   cudaFuncAttributeMaxDynamicSharedMemorySize, smem1);
    cudaFuncSetAttribute(k2_attn,  cudaFuncAttributeMaxDynamicSharedMemorySize, smem2);
    cudaFuncSetAttribute(k3_proj,  cudaFuncAttributeMaxDynamicSharedMemorySize, smem3);
    cudaFuncSetAttribute(k4a_ffn1, cudaFuncAttributeMaxDynamicSharedMemorySize, smem3);
    cudaFuncSetAttribute(k4b_ffn2, cudaFuncAttributeMaxDynamicSharedMemorySize, smem3);

    k1_qkv  <<<MTOK / 64, 256, smem1>>>(x, bng, bnb, bnm, bnv, qkvw, qkvb);
    k2_attn <<<NWIN * NHEAD, 256, smem2>>>();
    k3_proj <<<dim3(MTOK / 64, 2), 256, smem3>>>(x, pw, pb);
    k4a_ffn1<<<MTOK / 64, 256, smem3>>>(lng, lnb, w1, b1);
    k4b_ffn2<<<dim3(MTOK / 64, 2), 256, smem3>>>(w2, b2, out);
}

// round 4
// speedup vs baseline: 4.8146x; 4.8146x over previous
#include <cuda_runtime.h>
#include <cuda_bf16.h>
#include <math.h>
#include <stdint.h>

// ---------------- problem constants ----------------
constexpr int CC   = 128;      // channels
constexpr int CT   = 16;
constexpr int CH   = 56;
constexpr int CW   = 56;
constexpr int NTOK = 196;      // tokens per window (4*7*7)
constexpr int NWIN = 1024;     // B * 4*8*8
constexpr int MTOK = NWIN * NTOK;     // 200704 total tokens
constexpr int SPT  = CT * CH * CW;    // 50176 spatial per batch
constexpr int HW   = CH * CW;         // 3136

// ---------------- scratch (device globals; no runtime alloc) ----------------
__device__ __nv_bfloat16 g_qkv[(size_t)MTOK * 384];
__device__ __nv_bfloat16 g_att[(size_t)MTOK * 128];
__device__ float         g_y1 [(size_t)MTOK * 128];   // after first residual (token-major)
__device__ __nv_bfloat16 g_hid[(size_t)MTOK * 512];
// bf16 transposed weights [n][k]
__device__ __nv_bfloat16 g_wqkvT[384 * 128];
__device__ __nv_bfloat16 g_wpT  [128 * 128];
__device__ __nv_bfloat16 g_w1T  [512 * 128];
__device__ __nv_bfloat16 g_w2T  [128 * 512];

__device__ __forceinline__ void row_to_bsp(int R, int &b, int &sp) {
    int w = R / NTOK, n = R - w * NTOK;
    b = w >> 8;
    int rw = w & 255;
    int it = rw >> 6, ih = (rw >> 3) & 7, iw = rw & 7;
    int tt = n / 49;
    int rn = n - tt * 49;
    int hh = rn / 7, ww = rn - hh * 7;
    sp = (it * 4 + tt) * HW + (ih * 7 + hh) * CW + (iw * 7 + ww);
}

__device__ __forceinline__ void mma4(float* d, uint32_t a0, uint32_t a1, uint32_t a2, uint32_t a3,
                                     uint32_t b0, uint32_t b1) {
    asm volatile(
        "mma.sync.aligned.m16n8k16.row.col.f32.bf16.bf16.f32 "
        "{%0,%1,%2,%3},{%4,%5,%6,%7},{%8,%9},{%0,%1,%2,%3};"
        : "+f"(d[0]), "+f"(d[1]), "+f"(d[2]), "+f"(d[3])
        : "r"(a0), "r"(a1), "r"(a2), "r"(a3), "r"(b0), "r"(b1));
}

__device__ __forceinline__ uint32_t packbf(float x, float y) {
    __nv_bfloat162 t = __floats2bfloat162_rn(x, y);
    return *reinterpret_cast<uint32_t*>(&t);
}
__device__ __forceinline__ void st_bf2(__nv_bfloat16* p, float x, float y) {
    __nv_bfloat162 t = __floats2bfloat162_rn(x, y);
    *reinterpret_cast<__nv_bfloat162*>(p) = t;
}

constexpr int PA = 136;   // smem pitch (bf16 elems) for A/B tiles

// =====================================================================
// K0: weight transpose + bf16 convert
// =====================================================================
__global__ void kprep(const float* __restrict__ qkvw, const float* __restrict__ pw,
                      const float* __restrict__ w1,   const float* __restrict__ w2)
{
    int i = blockIdx.x * 256 + threadIdx.x;
    if (i < 49152) { int n = i >> 7, k = i & 127; g_wqkvT[n * 128 + k] = __float2bfloat16(qkvw[k * 384 + n]); return; }
    i -= 49152;
    if (i < 16384) { int n = i >> 7, k = i & 127; g_wpT[n * 128 + k] = __float2bfloat16(pw[k * 128 + n]); return; }
    i -= 16384;
    if (i < 65536) { int n = i >> 7, k = i & 127; g_w1T[n * 128 + k] = __float2bfloat16(w1[k * 512 + n]); return; }
    i -= 65536;
    if (i < 65536) { int n = i >> 9, k = i & 511; g_w2T[n * 512 + k] = __float2bfloat16(w2[k * 128 + n]); return; }
}

// =====================================================================
// K1: BN + window gather + qkv GEMM (M=200704, K=128, N=384), bf16 mma
// CTA: 128 rows, 6 x 64-col tiles. 256 thr = 8 warps (4m x 2n), warp 32x32
// =====================================================================
__global__ __launch_bounds__(256) void k1_qkv(
    const float* __restrict__ x,
    const float* __restrict__ bng, const float* __restrict__ bnb,
    const float* __restrict__ bnm, const float* __restrict__ bnv,
    const float* __restrict__ bq)
{
    extern __shared__ unsigned char shraw[];
    __nv_bfloat16* As = (__nv_bfloat16*)shraw;        // [128][PA]
    __nv_bfloat16* Bs = As + 128 * PA;                // [64][PA]  ([n][k])
    __shared__ float sc[128], sf[128];
    int tid = threadIdx.x;
    if (tid < 128) {
        float s = bng[tid] * rsqrtf(bnv[tid] + 1e-5f);
        sc[tid] = s;
        sf[tid] = bnb[tid] - bnm[tid] * s;
    }
    __syncthreads();

    int r = tid & 127, cs = tid >> 7;
    int R0 = blockIdx.x * 128;
    {
        int b, sp; row_to_bsp(R0 + r, b, sp);
        const float* xp = x + (size_t)b * 128 * SPT + sp + (size_t)cs * 64 * SPT;
        #pragma unroll 8
        for (int j = 0; j < 64; j++) {
            int c = cs * 64 + j;
            As[r * PA + c] = __float2bfloat16(xp[(size_t)j * SPT] * sc[c] + sf[c]);
        }
    }

    int w = tid >> 5, l = tid & 31;
    int mw = (w >> 1) * 32, nw = (w & 1) * 32;
    int rA = mw + (l >> 2), rB = nw + (l >> 2), kq = (l & 3) * 2;

    for (int nt = 0; nt < 6; nt++) {
        __syncthreads();
        for (int i = tid; i < 64 * 16; i += 256) {
            int n = i >> 4, seg = i & 15;
            *(uint4*)&Bs[n * PA + seg * 8] = *(const uint4*)&g_wqkvT[(nt * 64 + n) * 128 + seg * 8];
        }
        __syncthreads();
        float acc[2][4][4];
        #pragma unroll
        for (int a = 0; a < 2; a++)
            #pragma unroll
            for (int bb = 0; bb < 4; bb++)
                acc[a][bb][0] = acc[a][bb][1] = acc[a][bb][2] = acc[a][bb][3] = 0.f;

        #pragma unroll
        for (int k0 = 0; k0 < 128; k0 += 16) {
            uint32_t a[2][4];
            #pragma unroll
            for (int mt = 0; mt < 2; mt++) {
                int rr = rA + mt * 16;
                a[mt][0] = *(const uint32_t*)&As[rr * PA + k0 + kq];
                a[mt][1] = *(const uint32_t*)&As[(rr + 8) * PA + k0 + kq];
                a[mt][2] = *(const uint32_t*)&As[rr * PA + k0 + kq + 8];
                a[mt][3] = *(const uint32_t*)&As[(rr + 8) * PA + k0 + kq + 8];
            }
            #pragma unroll
            for (int ntb = 0; ntb < 4; ntb++) {
                uint32_t b0 = *(const uint32_t*)&Bs[(rB + ntb * 8) * PA + k0 + kq];
                uint32_t b1 = *(const uint32_t*)&Bs[(rB + ntb * 8) * PA + k0 + kq + 8];
                mma4(acc[0][ntb], a[0][0], a[0][1], a[0][2], a[0][3], b0, b1);
                mma4(acc[1][ntb], a[1][0], a[1][1], a[1][2], a[1][3], b0, b1);
            }
        }
        #pragma unroll
        for (int ntb = 0; ntb < 4; ntb++) {
            int cg = nt * 64 + nw + ntb * 8 + kq;
            float bx = bq[cg], by = bq[cg + 1];
            #pragma unroll
            for (int mt = 0; mt < 2; mt++) {
                int r0 = R0 + mw + mt * 16 + (l >> 2);
                st_bf2(&g_qkv[(size_t)r0 * 384 + cg],       acc[mt][ntb][0] + bx, acc[mt][ntb][1] + by);
                st_bf2(&g_qkv[(size_t)(r0 + 8) * 384 + cg], acc[mt][ntb][2] + bx, acc[mt][ntb][3] + by);
            }
        }
    }
}

// =====================================================================
// K2: attention per (window, head) with tensor cores.
// grid = 4096, 128 thr (4 warps). S held in registers; P->A-frag chaining.
// =====================================================================
constexpr int PQ = 34;    // Qs/Ks pitch
constexpr int PV = 212;   // Vt pitch

__global__ __launch_bounds__(128) void k2_attn()
{
    __shared__ __nv_bfloat16 Qs[208 * PQ];
    __shared__ __nv_bfloat16 Ks[208 * PQ];
    __shared__ __nv_bfloat16 Vt[32 * PV];
    int w = blockIdx.x >> 2, head = blockIdx.x & 3;
    int tid = threadIdx.x, l = tid & 31, wid = tid >> 5;
    int qbase = w * NTOK, coff = head * 32;

    for (int i = tid; i < 208 * 32; i += 128) {
        int n = i >> 5, d = i & 31;
        __nv_bfloat16 qv, kv, vv;
        if (n < NTOK) {
            const __nv_bfloat16* p = &g_qkv[(size_t)(qbase + n) * 384 + coff + d];
            qv = p[0]; kv = p[128]; vv = p[256];
        } else {
            qv = __float2bfloat16(0.f); kv = qv; vv = qv;
        }
        Qs[n * PQ + d] = qv;
        Ks[n * PQ + d] = kv;
        Vt[d * PV + n] = vv;
    }
    __syncthreads();

    const float scale = 0.17677669529663687f;
    int kq = (l & 3) * 2;

    for (int mt = wid; mt < 13; mt += 4) {
        int m0 = mt * 16;
        float S[26][4];
        #pragma unroll
        for (int t = 0; t < 26; t++) S[t][0] = S[t][1] = S[t][2] = S[t][3] = 0.f;

        int rA = m0 + (l >> 2);
        #pragma unroll
        for (int k0 = 0; k0 < 32; k0 += 16) {
            uint32_t a0 = *(const uint32_t*)&Qs[rA * PQ + k0 + kq];
            uint32_t a1 = *(const uint32_t*)&Qs[(rA + 8) * PQ + k0 + kq];
            uint32_t a2 = *(const uint32_t*)&Qs[rA * PQ + k0 + kq + 8];
            uint32_t a3 = *(const uint32_t*)&Qs[(rA + 8) * PQ + k0 + kq + 8];
            #pragma unroll
            for (int t = 0; t < 26; t++) {
                uint32_t b0 = *(const uint32_t*)&Ks[(t * 8 + (l >> 2)) * PQ + k0 + kq];
                uint32_t b1 = *(const uint32_t*)&Ks[(t * 8 + (l >> 2)) * PQ + k0 + kq + 8];
                mma4(S[t], a0, a1, a2, a3, b0, b1);
            }
        }

        // row softmax: rows r0 = l>>2 (regs 0,1), r1 = r0+8 (regs 2,3)
        float mx0 = -1e30f, mx1 = -1e30f;
        #pragma unroll
        for (int t = 0; t < 26; t++) {
            int c = t * 8 + kq;
            if (c < NTOK)     { mx0 = fmaxf(mx0, S[t][0]); mx1 = fmaxf(mx1, S[t][2]); }
            if (c + 1 < NTOK) { mx0 = fmaxf(mx0, S[t][1]); mx1 = fmaxf(mx1, S[t][3]); }
        }
        mx0 = fmaxf(mx0, __shfl_xor_sync(0xffffffffu, mx0, 1));
        mx0 = fmaxf(mx0, __shfl_xor_sync(0xffffffffu, mx0, 2));
        mx1 = fmaxf(mx1, __shfl_xor_sync(0xffffffffu, mx1, 1));
        mx1 = fmaxf(mx1, __shfl_xor_sync(0xffffffffu, mx1, 2));

        float s0 = 0.f, s1 = 0.f;
        #pragma unroll
        for (int t = 0; t < 26; t++) {
            int c = t * 8 + kq;
            if (c < NTOK)     { S[t][0] = __expf(scale * (S[t][0] - mx0)); s0 += S[t][0];
                                S[t][2] = __expf(scale * (S[t][2] - mx1)); s1 += S[t][2]; }
            else              { S[t][0] = 0.f; S[t][2] = 0.f; }
            if (c + 1 < NTOK) { S[t][1] = __expf(scale * (S[t][1] - mx0)); s0 += S[t][1];
                                S[t][3] = __expf(scale * (S[t][3] - mx1)); s1 += S[t][3]; }
            else              { S[t][1] = 0.f; S[t][3] = 0.f; }
        }
        s0 += __shfl_xor_sync(0xffffffffu, s0, 1);
        s0 += __shfl_xor_sync(0xffffffffu, s0, 2);
        s1 += __shfl_xor_sync(0xffffffffu, s1, 1);
        s1 += __shfl_xor_sync(0xffffffffu, s1, 2);
        float i0 = 1.f / s0, i1 = 1.f / s1;
        #pragma unroll
        for (int t = 0; t < 26; t++) {
            S[t][0] *= i0; S[t][1] *= i0; S[t][2] *= i1; S[t][3] *= i1;
        }

        // O = P @ V : chain D-frags -> A-frags, B from Vt [d][tok]
        float O[4][4];
        #pragma unroll
        for (int nt = 0; nt < 4; nt++) O[nt][0] = O[nt][1] = O[nt][2] = O[nt][3] = 0.f;
        #pragma unroll
        for (int kt = 0; kt < 13; kt++) {
            uint32_t pa0 = packbf(S[2 * kt][0],     S[2 * kt][1]);
            uint32_t pa1 = packbf(S[2 * kt][2],     S[2 * kt][3]);
            uint32_t pa2 = packbf(S[2 * kt + 1][0], S[2 * kt + 1][1]);
            uint32_t pa3 = packbf(S[2 * kt + 1][2], S[2 * kt + 1][3]);
            #pragma unroll
            for (int nt = 0; nt < 4; nt++) {
                uint32_t b0 = *(const uint32_t*)&Vt[(nt * 8 + (l >> 2)) * PV + kt * 16 + kq];
                uint32_t b1 = *(const uint32_t*)&Vt[(nt * 8 + (l >> 2)) * PV + kt * 16 + kq + 8];
                mma4(O[nt], pa0, pa1, pa2, pa3, b0, b1);
            }
        }

        int qr0 = m0 + (l >> 2), qr1 = qr0 + 8;
        #pragma unroll
        for (int nt = 0; nt < 4; nt++) {
            int cd = coff + nt * 8 + kq;
            if (qr0 < NTOK) st_bf2(&g_att[(size_t)(qbase + qr0) * 128 + cd], O[nt][0], O[nt][1]);
            if (qr1 < NTOK) st_bf2(&g_att[(size_t)(qbase + qr1) * 128 + cd], O[nt][2], O[nt][3]);
        }
    }
}

// =====================================================================
// K3: proj GEMM + window reverse + residual(x) -> y1 (token-major fp32)
// grid (1568, 2), CTA 128 x 64
// =====================================================================
__global__ __launch_bounds__(256) void k3_proj(
    const float* __restrict__ x, const float* __restrict__ bp)
{
    extern __shared__ unsigned char shraw[];
    __nv_bfloat16* As = (__nv_bfloat16*)shraw;
    __nv_bfloat16* Bs = As + 128 * PA;
    int tid = threadIdx.x;
    int R0 = blockIdx.x * 128;
    int col0 = blockIdx.y * 64;

    for (int i = tid; i < 128 * 16; i += 256) {
        int rl = i >> 4, seg = i & 15;
        *(uint4*)&As[rl * PA + seg * 8] = *(const uint4*)&g_att[(size_t)(R0 + rl) * 128 + seg * 8];
    }
    for (int i = tid; i < 64 * 16; i += 256) {
        int n = i >> 4, seg = i & 15;
        *(uint4*)&Bs[n * PA + seg * 8] = *(const uint4*)&g_wpT[(col0 + n) * 128 + seg * 8];
    }
    __syncthreads();

    int w = tid >> 5, l = tid & 31;
    int mw = (w >> 1) * 32, nw = (w & 1) * 32;
    int rA = mw + (l >> 2), rB = nw + (l >> 2), kq = (l & 3) * 2;

    float acc[2][4][4];
    #pragma unroll
    for (int a = 0; a < 2; a++)
        #pragma unroll
        for (int bb = 0; bb < 4; bb++)
            acc[a][bb][0] = acc[a][bb][1] = acc[a][bb][2] = acc[a][bb][3] = 0.f;

    #pragma unroll
    for (int k0 = 0; k0 < 128; k0 += 16) {
        uint32_t a[2][4];
        #pragma unroll
        for (int mt = 0; mt < 2; mt++) {
            int rr = rA + mt * 16;
            a[mt][0] = *(const uint32_t*)&As[rr * PA + k0 + kq];
            a[mt][1] = *(const uint32_t*)&As[(rr + 8) * PA + k0 + kq];
            a[mt][2] = *(const uint32_t*)&As[rr * PA + k0 + kq + 8];
            a[mt][3] = *(const uint32_t*)&As[(rr + 8) * PA + k0 + kq + 8];
        }
        #pragma unroll
        for (int ntb = 0; ntb < 4; ntb++) {
            uint32_t b0 = *(const uint32_t*)&Bs[(rB + ntb * 8) * PA + k0 + kq];
            uint32_t b1 = *(const uint32_t*)&Bs[(rB + ntb * 8) * PA + k0 + kq + 8];
            mma4(acc[0][ntb], a[0][0], a[0][1], a[0][2], a[0][3], b0, b1);
            mma4(acc[1][ntb], a[1][0], a[1][1], a[1][2], a[1][3], b0, b1);
        }
    }

    #pragma unroll
    for (int mt = 0; mt < 2; mt++) {
        #pragma unroll
        for (int half = 0; half < 2; half++) {
            int Rr = R0 + mw + mt * 16 + (l >> 2) + half * 8;
            int b, sp; row_to_bsp(Rr, b, sp);
            size_t xb = (size_t)b * 128 * SPT + sp;
            size_t tok = (size_t)(b * SPT + sp);
            #pragma unroll
            for (int ntb = 0; ntb < 4; ntb++) {
                int cg = col0 + nw + ntb * 8 + kq;
                float vx0 = x[xb + (size_t)cg * SPT];
                float vx1 = x[xb + (size_t)(cg + 1) * SPT];
                float2 o;
                o.x = acc[mt][ntb][half * 2 + 0] + bp[cg]     + vx0;
                o.y = acc[mt][ntb][half * 2 + 1] + bp[cg + 1] + vx1;
                *(float2*)&g_y1[tok * 128 + cg] = o;
            }
        }
    }
}

// =====================================================================
// K4a: LN + fc1 + exact GELU -> g_hid (M x 512). grid 1568, CTA 128x(8x64)
// =====================================================================
__global__ __launch_bounds__(256) void k4a_ffn1(
    const float* __restrict__ lng, const float* __restrict__ lnb,
    const float* __restrict__ b1)
{
    extern __shared__ unsigned char shraw[];
    __nv_bfloat16* As = (__nv_bfloat16*)shraw;
    __nv_bfloat16* Bs = As + 128 * PA;
    int tid = threadIdx.x;
    int R0 = blockIdx.x * 128;

    // LN: 2 threads per row, 64 channels each
    {
        int row = tid >> 1, seg = tid & 1;
        const float* src = &g_y1[(size_t)(R0 + row) * 128 + seg * 64];
        float s1 = 0.f, s2 = 0.f;
        #pragma unroll
        for (int j = 0; j < 64; j += 4) {
            float4 t = *(const float4*)&src[j];
            s1 += t.x + t.y + t.z + t.w;
            s2 += t.x * t.x + t.y * t.y + t.z * t.z + t.w * t.w;
        }
        s1 += __shfl_xor_sync(0xffffffffu, s1, 1);
        s2 += __shfl_xor_sync(0xffffffffu, s2, 1);
        float mean = s1 * (1.f / 128.f);
        float var  = s2 * (1.f / 128.f) - mean * mean;
        float rstd = rsqrtf(var + 1e-5f);
        #pragma unroll
        for (int j = 0; j < 64; j += 2) {
            int c = seg * 64 + j;
            float v0 = (src[j]     - mean) * rstd * lng[c]     + lnb[c];
            float v1 = (src[j + 1] - mean) * rstd * lng[c + 1] + lnb[c + 1];
            *(uint32_t*)&As[row * PA + c] = packbf(v0, v1);
        }
    }

    int w = tid >> 5, l = tid & 31;
    int mw = (w >> 1) * 32, nw = (w & 1) * 32;
    int rA = mw + (l >> 2), rB = nw + (l >> 2), kq = (l & 3) * 2;

    for (int nt = 0; nt < 8; nt++) {
        __syncthreads();
        for (int i = tid; i < 64 * 16; i += 256) {
            int n = i >> 4, seg = i & 15;
            *(uint4*)&Bs[n * PA + seg * 8] = *(const uint4*)&g_w1T[(nt * 64 + n) * 128 + seg * 8];
        }
        __syncthreads();
        float acc[2][4][4];
        #pragma unroll
        for (int a = 0; a < 2; a++)
            #pragma unroll
            for (int bb = 0; bb < 4; bb++)
                acc[a][bb][0] = acc[a][bb][1] = acc[a][bb][2] = acc[a][bb][3] = 0.f;

        #pragma unroll
        for (int k0 = 0; k0 < 128; k0 += 16) {
            uint32_t a[2][4];
            #pragma unroll
            for (int mt = 0; mt < 2; mt++) {
                int rr = rA + mt * 16;
                a[mt][0] = *(const uint32_t*)&As[rr * PA + k0 + kq];
                a[mt][1] = *(const uint32_t*)&As[(rr + 8) * PA + k0 + kq];
                a[mt][2] = *(const uint32_t*)&As[rr * PA + k0 + kq + 8];
                a[mt][3] = *(const uint32_t*)&As[(rr + 8) * PA + k0 + kq + 8];
            }
            #pragma unroll
            for (int ntb = 0; ntb < 4; ntb++) {
                uint32_t b0 = *(const uint32_t*)&Bs[(rB + ntb * 8) * PA + k0 + kq];
                uint32_t b1 = *(const uint32_t*)&Bs[(rB + ntb * 8) * PA + k0 + kq + 8];
                mma4(acc[0][ntb], a[0][0], a[0][1], a[0][2], a[0][3], b0, b1);
                mma4(acc[1][ntb], a[1][0], a[1][1], a[1][2], a[1][3], b0, b1);
            }
        }
        #pragma unroll
        for (int ntb = 0; ntb < 4; ntb++) {
            int cg = nt * 64 + nw + ntb * 8 + kq;
            float bx = b1[cg], by = b1[cg + 1];
            #pragma unroll
            for (int mt = 0; mt < 2; mt++) {
                #pragma unroll
                for (int half = 0; half < 2; half++) {
                    int r0 = R0 + mw + mt * 16 + (l >> 2) + half * 8;
                    float h0 = acc[mt][ntb][half * 2 + 0] + bx;
                    float h1 = acc[mt][ntb][half * 2 + 1] + by;
                    float g0 = 0.5f * h0 * (1.f + erff(h0 * 0.70710678118654752f));
                    float g1 = 0.5f * h1 * (1.f + erff(h1 * 0.70710678118654752f));
                    st_bf2(&g_hid[(size_t)r0 * 512 + cg], g0, g1);
                }
            }
        }
    }
}

// =====================================================================
// K4b: fc2 + residual(y1) + transposed store to (B,C,T,H,W).
// grid 1568, CTA 128 x 128, K=512 in 4 chunks. Warp: 32 x 64 (2 n-tiles).
// =====================================================================
__global__ __launch_bounds__(256) void k4b_ffn2(
    const float* __restrict__ b2, float* __restrict__ out)
{
    extern __shared__ unsigned char shraw[];
    __nv_bfloat16* As = (__nv_bfloat16*)shraw;       // [128][PA]
    __nv_bfloat16* Bs = As + 128 * PA;               // [128][PA]
    int tid = threadIdx.x;
    int R0 = blockIdx.x * 128;

    int w = tid >> 5, l = tid & 31;
    int mw = (w >> 1) * 32, nwl = (w & 1) * 32;
    int rA = mw + (l >> 2), kq = (l & 3) * 2;

    float acc[2][2][4][4];   // [mt][t(64-col half)][ntb][4]
    #pragma unroll
    for (int a = 0; a < 2; a++)
        #pragma unroll
        for (int t = 0; t < 2; t++)
            #pragma unroll
            for (int bb = 0; bb < 4; bb++)
                acc[a][t][bb][0] = acc[a][t][bb][1] = acc[a][t][bb][2] = acc[a][t][bb][3] = 0.f;

    for (int kc = 0; kc < 4; kc++) {
        __syncthreads();
        for (int i = tid; i < 128 * 16; i += 256) {
            int rl = i >> 4, seg = i & 15;
            *(uint4*)&As[rl * PA + seg * 8] = *(const uint4*)&g_hid[(size_t)(R0 + rl) * 512 + kc * 128 + seg * 8];
        }
        for (int i = tid; i < 128 * 16; i += 256) {
            int n = i >> 4, seg = i & 15;
            *(uint4*)&Bs[n * PA + seg * 8] = *(const uint4*)&g_w2T[n * 512 + kc * 128 + seg * 8];
        }
        __syncthreads();
        #pragma unroll
        for (int k0 = 0; k0 < 128; k0 += 16) {
            uint32_t a[2][4];
            #pragma unroll
            for (int mt = 0; mt < 2; mt++) {
                int rr = rA + mt * 16;
                a[mt][0] = *(const uint32_t*)&As[rr * PA + k0 + kq];
                a[mt][1] = *(const uint32_t*)&As[(rr + 8) * PA + k0 + kq];
                a[mt][2] = *(const uint32_t*)&As[rr * PA + k0 + kq + 8];
                a[mt][3] = *(const uint32_t*)&As[(rr + 8) * PA + k0 + kq + 8];
            }
            #pragma unroll
            for (int t = 0; t < 2; t++) {
                #pragma unroll
                for (int ntb = 0; ntb < 4; ntb++) {
                    int nr = t * 64 + nwl + ntb * 8 + (l >> 2);
                    uint32_t b0 = *(const uint32_t*)&Bs[nr * PA + k0 + kq];
                    uint32_t b1 = *(const uint32_t*)&Bs[nr * PA + k0 + kq + 8];
                    mma4(acc[0][t][ntb], a[0][0], a[0][1], a[0][2], a[0][3], b0, b1);
                    mma4(acc[1][t][ntb], a[1][0], a[1][1], a[1][2], a[1][3], b0, b1);
                }
            }
        }
    }

    __syncthreads();
    float* Cs = (float*)shraw;    // [128][133]
    #pragma unroll
    for (int mt = 0; mt < 2; mt++) {
        #pragma unroll
        for (int half = 0; half < 2; half++) {
            int row = mw + mt * 16 + (l >> 2) + half * 8;
            #pragma unroll
            for (int t = 0; t < 2; t++) {
                #pragma unroll
                for (int ntb = 0; ntb < 4; ntb++) {
                    int c = t * 64 + nwl + ntb * 8 + kq;
                    float2 yv = *(const float2*)&g_y1[(size_t)(R0 + row) * 128 + c];
                    Cs[row * 133 + c]     = acc[mt][t][ntb][half * 2 + 0] + b2[c]     + yv.x;
                    Cs[row * 133 + c + 1] = acc[mt][t][ntb][half * 2 + 1] + b2[c + 1] + yv.y;
                }
            }
        }
    }
    __syncthreads();

    int rl = tid & 127, cg = tid >> 7;
    int R = R0 + rl;
    int b = R / SPT, sp = R - b * SPT;
    size_t obase = (size_t)b * 128 * SPT + sp;
    #pragma unroll 8
    for (int j = 0; j < 64; j++) {
        int col = cg * 64 + j;
        out[obase + (size_t)col * SPT] = Cs[rl * 133 + col];
    }
}

// =====================================================================
extern "C" void kernel_launch(void* const* d_in, const int* in_sizes, int n_in,
                              void* d_out, int out_size)
{
    const float* x    = (const float*)d_in[0];
    const float* bng  = (const float*)d_in[1];
    const float* bnb  = (const float*)d_in[2];
    const float* bnm  = (const float*)d_in[3];
    const float* bnv  = (const float*)d_in[4];
    const float* qkvw = (const float*)d_in[5];
    const float* qkvb = (const float*)d_in[6];
    const float* pw   = (const float*)d_in[7];
    const float* pb   = (const float*)d_in[8];
    const float* lng  = (const float*)d_in[9];
    const float* lnb  = (const float*)d_in[10];
    const float* w1   = (const float*)d_in[11];
    const float* b1   = (const float*)d_in[12];
    const float* w2   = (const float*)d_in[13];
    const float* b2   = (const float*)d_in[14];
    float* out = (float*)d_out;

    const int smemAB  = (128 * PA + 64 * PA) * 2;     // 52224 B
    const int smem4b  = (128 * PA + 128 * PA) * 2;    // 69632 B

    cudaFuncSetAttribute(k1_qkv,   cudaFuncAttributeMaxDynamicSharedMemorySize, smemAB);
    cudaFuncSetAttribute(k3_proj,  cudaFuncAttributeMaxDynamicSharedMemorySize, smemAB);
    cudaFuncSetAttribute(k4a_ffn1, cudaFuncAttributeMaxDynamicSharedMemorySize, smemAB);
    cudaFuncSetAttribute(k4b_ffn2, cudaFuncAttributeMaxDynamicSharedMemorySize, smem4b);

    kprep   <<<768, 256>>>(qkvw, pw, w1, w2);
    k1_qkv  <<<MTOK / 128, 256, smemAB>>>(x, bng, bnb, bnm, bnv, qkvb);
    k2_attn <<<NWIN * 4, 128>>>();
    k3_proj <<<dim3(MTOK / 128, 2), 256, smemAB>>>(x, pb);
    k4a_ffn1<<<MTOK / 128, 256, smemAB>>>(lng, lnb, b1);
    k4b_ffn2<<<MTOK / 128, 256, smem4b>>>(b2, out);
}

// round 5
// speedup vs baseline: 4.9687x; 1.0320x over previous
#include <cuda_runtime.h>
#include <cuda_bf16.h>
#include <math.h>
#include <stdint.h>

// ---------------- problem constants ----------------
constexpr int CC   = 128;
constexpr int CT   = 16;
constexpr int CH   = 56;
constexpr int CW   = 56;
constexpr int NTOK = 196;
constexpr int NWIN = 1024;
constexpr int MTOK = NWIN * NTOK;     // 200704
constexpr int SPT  = CT * CH * CW;    // 50176
constexpr int HW   = CH * CW;         // 3136

// ---------------- scratch ----------------
__device__ __nv_bfloat16 g_qkv[(size_t)MTOK * 384];
__device__ float         g_y1 [(size_t)MTOK * 128];
__device__ __nv_bfloat16 g_wqkvT[384 * 128];
__device__ __nv_bfloat16 g_wpT  [128 * 128];
__device__ __nv_bfloat16 g_w1T  [512 * 128];
__device__ __nv_bfloat16 g_w2T  [128 * 512];

__device__ __forceinline__ void row_to_bsp(int R, int &b, int &sp) {
    int w = R / NTOK, n = R - w * NTOK;
    b = w >> 8;
    int rw = w & 255;
    int it = rw >> 6, ih = (rw >> 3) & 7, iw = rw & 7;
    int tt = n / 49;
    int rn = n - tt * 49;
    int hh = rn / 7, ww = rn - hh * 7;
    sp = (it * 4 + tt) * HW + (ih * 7 + hh) * CW + (iw * 7 + ww);
}

__device__ __forceinline__ void mma4(float* d, uint32_t a0, uint32_t a1, uint32_t a2, uint32_t a3,
                                     uint32_t b0, uint32_t b1) {
    asm volatile(
        "mma.sync.aligned.m16n8k16.row.col.f32.bf16.bf16.f32 "
        "{%0,%1,%2,%3},{%4,%5,%6,%7},{%8,%9},{%0,%1,%2,%3};"
        : "+f"(d[0]), "+f"(d[1]), "+f"(d[2]), "+f"(d[3])
        : "r"(a0), "r"(a1), "r"(a2), "r"(a3), "r"(b0), "r"(b1));
}

__device__ __forceinline__ uint32_t packbf(float x, float y) {
    __nv_bfloat162 t = __floats2bfloat162_rn(x, y);
    return *reinterpret_cast<uint32_t*>(&t);
}
__device__ __forceinline__ void st_bf2(__nv_bfloat16* p, float x, float y) {
    __nv_bfloat162 t = __floats2bfloat162_rn(x, y);
    *reinterpret_cast<__nv_bfloat162*>(p) = t;
}

constexpr int PA = 136;

// =====================================================================
// K0: weight transpose + bf16 convert
// =====================================================================
__global__ void kprep(const float* __restrict__ qkvw, const float* __restrict__ pw,
                      const float* __restrict__ w1,   const float* __restrict__ w2)
{
    int i = blockIdx.x * 256 + threadIdx.x;
    if (i < 49152) { int n = i >> 7, k = i & 127; g_wqkvT[n * 128 + k] = __float2bfloat16(qkvw[k * 384 + n]); return; }
    i -= 49152;
    if (i < 16384) { int n = i >> 7, k = i & 127; g_wpT[n * 128 + k] = __float2bfloat16(pw[k * 128 + n]); return; }
    i -= 16384;
    if (i < 65536) { int n = i >> 7, k = i & 127; g_w1T[n * 128 + k] = __float2bfloat16(w1[k * 512 + n]); return; }
    i -= 65536;
    if (i < 65536) { int n = i >> 9, k = i & 511; g_w2T[n * 512 + k] = __float2bfloat16(w2[k * 128 + n]); return; }
}

// =====================================================================
// K1: BN + window gather + qkv GEMM (unchanged from passing R4 version)
// =====================================================================
__global__ __launch_bounds__(256) void k1_qkv(
    const float* __restrict__ x,
    const float* __restrict__ bng, const float* __restrict__ bnb,
    const float* __restrict__ bnm, const float* __restrict__ bnv,
    const float* __restrict__ bq)
{
    extern __shared__ unsigned char shraw[];
    __nv_bfloat16* As = (__nv_bfloat16*)shraw;        // [128][PA]
    __nv_bfloat16* Bs = As + 128 * PA;                // [64][PA]
    __shared__ float sc[128], sf[128];
    int tid = threadIdx.x;
    if (tid < 128) {
        float s = bng[tid] * rsqrtf(bnv[tid] + 1e-5f);
        sc[tid] = s;
        sf[tid] = bnb[tid] - bnm[tid] * s;
    }
    __syncthreads();

    int r = tid & 127, cs = tid >> 7;
    int R0 = blockIdx.x * 128;
    {
        int b, sp; row_to_bsp(R0 + r, b, sp);
        const float* xp = x + (size_t)b * 128 * SPT + sp + (size_t)cs * 64 * SPT;
        #pragma unroll 8
        for (int j = 0; j < 64; j++) {
            int c = cs * 64 + j;
            As[r * PA + c] = __float2bfloat16(xp[(size_t)j * SPT] * sc[c] + sf[c]);
        }
    }

    int w = tid >> 5, l = tid & 31;
    int mw = (w >> 1) * 32, nw = (w & 1) * 32;
    int rA = mw + (l >> 2), rB = nw + (l >> 2), kq = (l & 3) * 2;

    for (int nt = 0; nt < 6; nt++) {
        __syncthreads();
        for (int i = tid; i < 64 * 16; i += 256) {
            int n = i >> 4, seg = i & 15;
            *(uint4*)&Bs[n * PA + seg * 8] = *(const uint4*)&g_wqkvT[(nt * 64 + n) * 128 + seg * 8];
        }
        __syncthreads();
        float acc[2][4][4];
        #pragma unroll
        for (int a = 0; a < 2; a++)
            #pragma unroll
            for (int bb = 0; bb < 4; bb++)
                acc[a][bb][0] = acc[a][bb][1] = acc[a][bb][2] = acc[a][bb][3] = 0.f;

        #pragma unroll
        for (int k0 = 0; k0 < 128; k0 += 16) {
            uint32_t a[2][4];
            #pragma unroll
            for (int mt = 0; mt < 2; mt++) {
                int rr = rA + mt * 16;
                a[mt][0] = *(const uint32_t*)&As[rr * PA + k0 + kq];
                a[mt][1] = *(const uint32_t*)&As[(rr + 8) * PA + k0 + kq];
                a[mt][2] = *(const uint32_t*)&As[rr * PA + k0 + kq + 8];
                a[mt][3] = *(const uint32_t*)&As[(rr + 8) * PA + k0 + kq + 8];
            }
            #pragma unroll
            for (int ntb = 0; ntb < 4; ntb++) {
                uint32_t b0 = *(const uint32_t*)&Bs[(rB + ntb * 8) * PA + k0 + kq];
                uint32_t b1 = *(const uint32_t*)&Bs[(rB + ntb * 8) * PA + k0 + kq + 8];
                mma4(acc[0][ntb], a[0][0], a[0][1], a[0][2], a[0][3], b0, b1);
                mma4(acc[1][ntb], a[1][0], a[1][1], a[1][2], a[1][3], b0, b1);
            }
        }
        #pragma unroll
        for (int ntb = 0; ntb < 4; ntb++) {
            int cg = nt * 64 + nw + ntb * 8 + kq;
            float bx = bq[cg], by = bq[cg + 1];
            #pragma unroll
            for (int mt = 0; mt < 2; mt++) {
                int r0 = R0 + mw + mt * 16 + (l >> 2);
                st_bf2(&g_qkv[(size_t)r0 * 384 + cg],       acc[mt][ntb][0] + bx, acc[mt][ntb][1] + by);
                st_bf2(&g_qkv[(size_t)(r0 + 8) * 384 + cg], acc[mt][ntb][2] + bx, acc[mt][ntb][3] + by);
            }
        }
    }
}

// =====================================================================
// K2': per-window attention (4 heads) + proj + residual -> y1.
// grid = 1024 windows, 256 threads (8 warps).
// =====================================================================
constexpr int PQ2 = 34;
constexpr int PVT = 216;
constexpr int PO  = 136;
constexpr int OFF_KS = 208 * PQ2;            // 7072
constexpr int OFF_VT = OFF_KS + 208 * PQ2;   // 14144
constexpr int OFF_O  = OFF_VT + 32 * PVT;    // 21056
constexpr int SM2_ELEMS = OFF_O + 208 * PO;  // 49344 bf16

__global__ __launch_bounds__(256) void k2_attnproj(
    const float* __restrict__ x, const float* __restrict__ bp)
{
    extern __shared__ unsigned char shraw[];
    __nv_bfloat16* sm = (__nv_bfloat16*)shraw;
    __nv_bfloat16* Qs = sm;
    __nv_bfloat16* Ks = sm + OFF_KS;
    __nv_bfloat16* Vt = sm + OFF_VT;
    __nv_bfloat16* Os = sm + OFF_O;

    int tid = threadIdx.x, l = tid & 31, wid = tid >> 5;
    int win = blockIdx.x;
    int qbase = win * NTOK;
    int kq = (l & 3) * 2;
    const float scale = 0.17677669529663687f;

    // zero O pad rows 196..207 (contiguous block)
    for (int i = tid; i < 12 * PO; i += 256) Os[196 * PO + i] = __float2bfloat16(0.f);

    for (int h = 0; h < 4; h++) {
        __syncthreads();
        int coff = h * 32;
        for (int i = tid; i < 208 * 32; i += 256) {
            int n = i >> 5, d = i & 31;
            __nv_bfloat16 qv, kv, vv;
            if (n < NTOK) {
                const __nv_bfloat16* p = &g_qkv[(size_t)(qbase + n) * 384 + coff + d];
                qv = p[0]; kv = p[128]; vv = p[256];
            } else {
                qv = __float2bfloat16(0.f); kv = qv; vv = qv;
            }
            Qs[n * PQ2 + d] = qv;
            Ks[n * PQ2 + d] = kv;
            Vt[d * PVT + n] = vv;
        }
        __syncthreads();

        for (int u = wid; u < 13; u += 8) {
            int m0 = u * 16;
            float S[26][4];
            #pragma unroll
            for (int t = 0; t < 26; t++) S[t][0] = S[t][1] = S[t][2] = S[t][3] = 0.f;

            int rA = m0 + (l >> 2);
            #pragma unroll
            for (int k0 = 0; k0 < 32; k0 += 16) {
                uint32_t a0 = *(const uint32_t*)&Qs[rA * PQ2 + k0 + kq];
                uint32_t a1 = *(const uint32_t*)&Qs[(rA + 8) * PQ2 + k0 + kq];
                uint32_t a2 = *(const uint32_t*)&Qs[rA * PQ2 + k0 + kq + 8];
                uint32_t a3 = *(const uint32_t*)&Qs[(rA + 8) * PQ2 + k0 + kq + 8];
                #pragma unroll
                for (int t = 0; t < 26; t++) {
                    uint32_t b0 = *(const uint32_t*)&Ks[(t * 8 + (l >> 2)) * PQ2 + k0 + kq];
                    uint32_t b1 = *(const uint32_t*)&Ks[(t * 8 + (l >> 2)) * PQ2 + k0 + kq + 8];
                    mma4(S[t], a0, a1, a2, a3, b0, b1);
                }
            }

            float mx0 = -1e30f, mx1 = -1e30f;
            #pragma unroll
            for (int t = 0; t < 26; t++) {
                int c = t * 8 + kq;
                if (c < NTOK)     { mx0 = fmaxf(mx0, S[t][0]); mx1 = fmaxf(mx1, S[t][2]); }
                if (c + 1 < NTOK) { mx0 = fmaxf(mx0, S[t][1]); mx1 = fmaxf(mx1, S[t][3]); }
            }
            mx0 = fmaxf(mx0, __shfl_xor_sync(0xffffffffu, mx0, 1));
            mx0 = fmaxf(mx0, __shfl_xor_sync(0xffffffffu, mx0, 2));
            mx1 = fmaxf(mx1, __shfl_xor_sync(0xffffffffu, mx1, 1));
            mx1 = fmaxf(mx1, __shfl_xor_sync(0xffffffffu, mx1, 2));

            float s0 = 0.f, s1 = 0.f;
            #pragma unroll
            for (int t = 0; t < 26; t++) {
                int c = t * 8 + kq;
                if (c < NTOK)     { S[t][0] = __expf(scale * (S[t][0] - mx0)); s0 += S[t][0];
                                    S[t][2] = __expf(scale * (S[t][2] - mx1)); s1 += S[t][2]; }
                else              { S[t][0] = 0.f; S[t][2] = 0.f; }
                if (c + 1 < NTOK) { S[t][1] = __expf(scale * (S[t][1] - mx0)); s0 += S[t][1];
                                    S[t][3] = __expf(scale * (S[t][3] - mx1)); s1 += S[t][3]; }
                else              { S[t][1] = 0.f; S[t][3] = 0.f; }
            }
            s0 += __shfl_xor_sync(0xffffffffu, s0, 1);
            s0 += __shfl_xor_sync(0xffffffffu, s0, 2);
            s1 += __shfl_xor_sync(0xffffffffu, s1, 1);
            s1 += __shfl_xor_sync(0xffffffffu, s1, 2);
            float i0 = 1.f / s0, i1 = 1.f / s1;
            #pragma unroll
            for (int t = 0; t < 26; t++) {
                S[t][0] *= i0; S[t][1] *= i0; S[t][2] *= i1; S[t][3] *= i1;
            }

            float O[4][4];
            #pragma unroll
            for (int nt = 0; nt < 4; nt++) O[nt][0] = O[nt][1] = O[nt][2] = O[nt][3] = 0.f;
            #pragma unroll
            for (int kt = 0; kt < 13; kt++) {
                uint32_t pa0 = packbf(S[2 * kt][0],     S[2 * kt][1]);
                uint32_t pa1 = packbf(S[2 * kt][2],     S[2 * kt][3]);
                uint32_t pa2 = packbf(S[2 * kt + 1][0], S[2 * kt + 1][1]);
                uint32_t pa3 = packbf(S[2 * kt + 1][2], S[2 * kt + 1][3]);
                #pragma unroll
                for (int nt = 0; nt < 4; nt++) {
                    uint32_t b0 = *(const uint32_t*)&Vt[(nt * 8 + (l >> 2)) * PVT + kt * 16 + kq];
                    uint32_t b1 = *(const uint32_t*)&Vt[(nt * 8 + (l >> 2)) * PVT + kt * 16 + kq + 8];
                    mma4(O[nt], pa0, pa1, pa2, pa3, b0, b1);
                }
            }

            int qr0 = m0 + (l >> 2), qr1 = qr0 + 8;
            #pragma unroll
            for (int nt = 0; nt < 4; nt++) {
                int cd = coff + nt * 8 + kq;
                if (qr0 < NTOK) st_bf2(&Os[qr0 * PO + cd], O[nt][0], O[nt][1]);
                if (qr1 < NTOK) st_bf2(&Os[qr1 * PO + cd], O[nt][2], O[nt][3]);
            }
        }
    }

    // ---- proj phase: y1 = Os @ WpT + bp + x ----
    __syncthreads();
    __nv_bfloat16* Bs = sm;   // alias Qs/Ks/Vt region (17408 <= 21056)
    for (int i = tid; i < 128 * 16; i += 256) {
        int n = i >> 4, seg = i & 15;
        *(uint4*)&Bs[n * PO + seg * 8] = *(const uint4*)&g_wpT[n * 128 + seg * 8];
    }
    __syncthreads();

    for (int u = wid; u < 13; u += 8) {
        int m0 = u * 16;
        float acc[16][4];
        #pragma unroll
        for (int t = 0; t < 16; t++) acc[t][0] = acc[t][1] = acc[t][2] = acc[t][3] = 0.f;
        int rA = m0 + (l >> 2);
        #pragma unroll
        for (int k0 = 0; k0 < 128; k0 += 16) {
            uint32_t a0 = *(const uint32_t*)&Os[rA * PO + k0 + kq];
            uint32_t a1 = *(const uint32_t*)&Os[(rA + 8) * PO + k0 + kq];
            uint32_t a2 = *(const uint32_t*)&Os[rA * PO + k0 + kq + 8];
            uint32_t a3 = *(const uint32_t*)&Os[(rA + 8) * PO + k0 + kq + 8];
            #pragma unroll
            for (int ntb = 0; ntb < 16; ntb++) {
                uint32_t b0 = *(const uint32_t*)&Bs[(ntb * 8 + (l >> 2)) * PO + k0 + kq];
                uint32_t b1 = *(const uint32_t*)&Bs[(ntb * 8 + (l >> 2)) * PO + k0 + kq + 8];
                mma4(acc[ntb], a0, a1, a2, a3, b0, b1);
            }
        }
        #pragma unroll
        for (int half = 0; half < 2; half++) {
            int row = m0 + (l >> 2) + half * 8;
            if (row < NTOK) {
                int b, sp; row_to_bsp(qbase + row, b, sp);
                size_t xb = (size_t)b * 128 * SPT + sp;
                size_t tok = (size_t)b * SPT + sp;
                #pragma unroll
                for (int ntb = 0; ntb < 16; ntb++) {
                    int cg = ntb * 8 + kq;
                    float2 o;
                    o.x = acc[ntb][half * 2 + 0] + bp[cg]     + x[xb + (size_t)cg * SPT];
                    o.y = acc[ntb][half * 2 + 1] + bp[cg + 1] + x[xb + (size_t)(cg + 1) * SPT];
                    *(float2*)&g_y1[tok * 128 + cg] = o;
                }
            }
        }
    }
}

// =====================================================================
// K4: fused LN + fc1 + GELU + fc2 + residual + transposed output.
// grid 1568, 256 thr. Hidden staged in smem in 4 chunks of 128.
// =====================================================================
constexpr int OFF_H4 = 128 * PA;       // 17408
constexpr int OFF_B4 = 2 * 128 * PA;   // 34816
constexpr int SM4_ELEMS = 3 * 128 * PA; // 52224 bf16

__global__ __launch_bounds__(256) void k4_ffn(
    const float* __restrict__ lng, const float* __restrict__ lnb,
    const float* __restrict__ b1,  const float* __restrict__ b2,
    float* __restrict__ out)
{
    extern __shared__ unsigned char shraw[];
    __nv_bfloat16* As = (__nv_bfloat16*)shraw;
    __nv_bfloat16* H  = As + OFF_H4;
    __nv_bfloat16* Bs = As + OFF_B4;
    int tid = threadIdx.x, l = tid & 31, w = tid >> 5;
    int R0 = blockIdx.x * 128;

    // LN -> As (bf16)
    {
        int row = tid >> 1, seg = tid & 1;
        const float* src = &g_y1[(size_t)(R0 + row) * 128 + seg * 64];
        float s1 = 0.f, s2 = 0.f;
        #pragma unroll
        for (int j = 0; j < 64; j += 4) {
            float4 t = *(const float4*)&src[j];
            s1 += t.x + t.y + t.z + t.w;
            s2 += t.x * t.x + t.y * t.y + t.z * t.z + t.w * t.w;
        }
        s1 += __shfl_xor_sync(0xffffffffu, s1, 1);
        s2 += __shfl_xor_sync(0xffffffffu, s2, 1);
        float mean = s1 * (1.f / 128.f);
        float var  = s2 * (1.f / 128.f) - mean * mean;
        float rstd = rsqrtf(var + 1e-5f);
        #pragma unroll
        for (int j = 0; j < 64; j += 2) {
            int c = seg * 64 + j;
            float v0 = (src[j]     - mean) * rstd * lng[c]     + lnb[c];
            float v1 = (src[j + 1] - mean) * rstd * lng[c + 1] + lnb[c + 1];
            *(uint32_t*)&As[row * PA + c] = packbf(v0, v1);
        }
    }

    int mw = (w >> 1) * 32, nw = (w & 1) * 32;
    int rA = mw + (l >> 2), kq = (l & 3) * 2;

    float acc2[2][2][4][4];
    #pragma unroll
    for (int a = 0; a < 2; a++)
        #pragma unroll
        for (int t = 0; t < 2; t++)
            #pragma unroll
            for (int bb = 0; bb < 4; bb++)
                acc2[a][t][bb][0] = acc2[a][t][bb][1] = acc2[a][t][bb][2] = acc2[a][t][bb][3] = 0.f;

    for (int kc = 0; kc < 4; kc++) {
        __syncthreads();
        // load W1 chunk (hidden cols kc*128 .. +128)
        for (int i = tid; i < 128 * 16; i += 256) {
            int n = i >> 4, seg = i & 15;
            *(uint4*)&Bs[n * PA + seg * 8] = *(const uint4*)&g_w1T[(size_t)(kc * 128 + n) * 128 + seg * 8];
        }
        __syncthreads();

        // fc1 + GELU -> H
        #pragma unroll
        for (int nt = 0; nt < 2; nt++) {
            float acc[2][4][4];
            #pragma unroll
            for (int a = 0; a < 2; a++)
                #pragma unroll
                for (int bb = 0; bb < 4; bb++)
                    acc[a][bb][0] = acc[a][bb][1] = acc[a][bb][2] = acc[a][bb][3] = 0.f;

            #pragma unroll
            for (int k0 = 0; k0 < 128; k0 += 16) {
                uint32_t a[2][4];
                #pragma unroll
                for (int mt = 0; mt < 2; mt++) {
                    int rr = rA + mt * 16;
                    a[mt][0] = *(const uint32_t*)&As[rr * PA + k0 + kq];
                    a[mt][1] = *(const uint32_t*)&As[(rr + 8) * PA + k0 + kq];
                    a[mt][2] = *(const uint32_t*)&As[rr * PA + k0 + kq + 8];
                    a[mt][3] = *(const uint32_t*)&As[(rr + 8) * PA + k0 + kq + 8];
                }
                #pragma unroll
                for (int ntb = 0; ntb < 4; ntb++) {
                    int nr = nt * 64 + nw + ntb * 8 + (l >> 2);
                    uint32_t b0 = *(const uint32_t*)&Bs[nr * PA + k0 + kq];
                    uint32_t b1 = *(const uint32_t*)&Bs[nr * PA + k0 + kq + 8];
                    mma4(acc[0][ntb], a[0][0], a[0][1], a[0][2], a[0][3], b0, b1);
                    mma4(acc[1][ntb], a[1][0], a[1][1], a[1][2], a[1][3], b0, b1);
                }
            }
            #pragma unroll
            for (int ntb = 0; ntb < 4; ntb++) {
                int cl = nt * 64 + nw + ntb * 8 + kq;
                float bx = b1[kc * 128 + cl], by = b1[kc * 128 + cl + 1];
                #pragma unroll
                for (int mt = 0; mt < 2; mt++) {
                    #pragma unroll
                    for (int half = 0; half < 2; half++) {
                        int row = mw + mt * 16 + (l >> 2) + half * 8;
                        float h0 = acc[mt][ntb][half * 2 + 0] + bx;
                        float h1 = acc[mt][ntb][half * 2 + 1] + by;
                        float g0 = 0.5f * h0 * (1.f + erff(h0 * 0.70710678118654752f));
                        float g1 = 0.5f * h1 * (1.f + erff(h1 * 0.70710678118654752f));
                        st_bf2(&H[row * PA + cl], g0, g1);
                    }
                }
            }
        }
        __syncthreads();
        // load W2 chunk (k rows kc*128 .. +128 of K=512)
        for (int i = tid; i < 128 * 16; i += 256) {
            int n = i >> 4, seg = i & 15;
            *(uint4*)&Bs[n * PA + seg * 8] = *(const uint4*)&g_w2T[(size_t)n * 512 + kc * 128 + seg * 8];
        }
        __syncthreads();
        // fc2 accumulate
        #pragma unroll
        for (int k0 = 0; k0 < 128; k0 += 16) {
            uint32_t a[2][4];
            #pragma unroll
            for (int mt = 0; mt < 2; mt++) {
                int rr = rA + mt * 16;
                a[mt][0] = *(const uint32_t*)&H[rr * PA + k0 + kq];
                a[mt][1] = *(const uint32_t*)&H[(rr + 8) * PA + k0 + kq];
                a[mt][2] = *(const uint32_t*)&H[rr * PA + k0 + kq + 8];
                a[mt][3] = *(const uint32_t*)&H[(rr + 8) * PA + k0 + kq + 8];
            }
            #pragma unroll
            for (int t = 0; t < 2; t++) {
                #pragma unroll
                for (int ntb = 0; ntb < 4; ntb++) {
                    int nr = t * 64 + nw + ntb * 8 + (l >> 2);
                    uint32_t b0 = *(const uint32_t*)&Bs[nr * PA + k0 + kq];
                    uint32_t b1 = *(const uint32_t*)&Bs[nr * PA + k0 + kq + 8];
                    mma4(acc2[0][t][ntb], a[0][0], a[0][1], a[0][2], a[0][3], b0, b1);
                    mma4(acc2[1][t][ntb], a[1][0], a[1][1], a[1][2], a[1][3], b0, b1);
                }
            }
        }
    }

    __syncthreads();
    float* Cs = (float*)shraw;   // [128][133] fp32, reuses As+H (68KB <= 69.6KB)
    #pragma unroll
    for (int mt = 0; mt < 2; mt++) {
        #pragma unroll
        for (int half = 0; half < 2; half++) {
            int row = mw + mt * 16 + (l >> 2) + half * 8;
            #pragma unroll
            for (int t = 0; t < 2; t++) {
                #pragma unroll
                for (int ntb = 0; ntb < 4; ntb++) {
                    int c = t * 64 + nw + ntb * 8 + kq;
                    float2 yv = *(const float2*)&g_y1[(size_t)(R0 + row) * 128 + c];
                    Cs[row * 133 + c]     = acc2[mt][t][ntb][half * 2 + 0] + b2[c]     + yv.x;
                    Cs[row * 133 + c + 1] = acc2[mt][t][ntb][half * 2 + 1] + b2[c + 1] + yv.y;
                }
            }
        }
    }
    __syncthreads();

    int rl = tid & 127, cg = tid >> 7;
    int R = R0 + rl;
    int b = R / SPT, sp = R - b * SPT;
    size_t obase = (size_t)b * 128 * SPT + sp;
    #pragma unroll 8
    for (int j = 0; j < 64; j++) {
        int col = cg * 64 + j;
        out[obase + (size_t)col * SPT] = Cs[rl * 133 + col];
    }
}

// =====================================================================
extern "C" void kernel_launch(void* const* d_in, const int* in_sizes, int n_in,
                              void* d_out, int out_size)
{
    const float* x    = (const float*)d_in[0];
    const float* bng  = (const float*)d_in[1];
    const float* bnb  = (const float*)d_in[2];
    const float* bnm  = (const float*)d_in[3];
    const float* bnv  = (const float*)d_in[4];
    const float* qkvw = (const float*)d_in[5];
    const float* qkvb = (const float*)d_in[6];
    const float* pw   = (const float*)d_in[7];
    const float* pb   = (const float*)d_in[8];
    const float* lng  = (const float*)d_in[9];
    const float* lnb  = (const float*)d_in[10];
    const float* w1   = (const float*)d_in[11];
    const float* b1   = (const float*)d_in[12];
    const float* w2   = (const float*)d_in[13];
    const float* b2   = (const float*)d_in[14];
    float* out = (float*)d_out;

    const int smem1 = (128 * PA + 64 * PA) * 2;   // 52224
    const int smem2 = SM2_ELEMS * 2;              // 98688
    const int smem4 = SM4_ELEMS * 2;              // 104448

    cudaFuncSetAttribute(k1_qkv,      cudaFuncAttributeMaxDynamicSharedMemorySize, smem1);
    cudaFuncSetAttribute(k2_attnproj, cudaFuncAttributeMaxDynamicSharedMemorySize, smem2);
    cudaFuncSetAttribute(k4_ffn,      cudaFuncAttributeMaxDynamicSharedMemorySize, smem4);

    kprep       <<<768, 256>>>(qkvw, pw, w1, w2);
    k1_qkv      <<<MTOK / 128, 256, smem1>>>(x, bng, bnb, bnm, bnv, qkvb);
    k2_attnproj <<<NWIN, 256, smem2>>>(x, pb);
    k4_ffn      <<<MTOK / 128, 256, smem4>>>(lng, lnb, b1, b2, out);
}

// round 7
// speedup vs baseline: 5.1180x; 1.0301x over previous
#include <cuda_runtime.h>
#include <cuda_bf16.h>
#include <math.h>
#include <stdint.h>

// ---------------- problem constants ----------------
constexpr int CC   = 128;
constexpr int CT   = 16;
constexpr int CH   = 56;
constexpr int CW   = 56;
constexpr int NTOK = 196;
constexpr int NWIN = 1024;
constexpr int MTOK = NWIN * NTOK;     // 200704
constexpr int SPT  = CT * CH * CW;    // 50176
constexpr int HW   = CH * CW;         // 3136

// ---------------- scratch ----------------
__device__ __nv_bfloat16 g_qkv[(size_t)MTOK * 384];
__device__ float         g_y1 [(size_t)MTOK * 128];
__device__ __nv_bfloat16 g_wqkvT[384 * 128];
__device__ __nv_bfloat16 g_wpT  [128 * 128];
__device__ __nv_bfloat16 g_w1T  [512 * 128];
__device__ __nv_bfloat16 g_w2T  [128 * 512];

__device__ __forceinline__ void row_to_bsp(int R, int &b, int &sp) {
    int w = R / NTOK, n = R - w * NTOK;
    b = w >> 8;
    int rw = w & 255;
    int it = rw >> 6, ih = (rw >> 3) & 7, iw = rw & 7;
    int tt = n / 49;
    int rn = n - tt * 49;
    int hh = rn / 7, ww = rn - hh * 7;
    sp = (it * 4 + tt) * HW + (ih * 7 + hh) * CW + (iw * 7 + ww);
}

__device__ __forceinline__ void mma4(float* d, uint32_t a0, uint32_t a1, uint32_t a2, uint32_t a3,
                                     uint32_t b0, uint32_t b1) {
    asm volatile(
        "mma.sync.aligned.m16n8k16.row.col.f32.bf16.bf16.f32 "
        "{%0,%1,%2,%3},{%4,%5,%6,%7},{%8,%9},{%0,%1,%2,%3};"
        : "+f"(d[0]), "+f"(d[1]), "+f"(d[2]), "+f"(d[3])
        : "r"(a0), "r"(a1), "r"(a2), "r"(a3), "r"(b0), "r"(b1));
}

__device__ __forceinline__ void ldsm4(uint32_t* r, uint32_t saddr) {
    asm volatile("ldmatrix.sync.aligned.m8n8.x4.shared.b16 {%0,%1,%2,%3}, [%4];"
        : "=r"(r[0]), "=r"(r[1]), "=r"(r[2]), "=r"(r[3]) : "r"(saddr));
}

__device__ __forceinline__ uint32_t s2u(const void* p) {
    return (uint32_t)__cvta_generic_to_shared(p);
}

__device__ __forceinline__ uint32_t packbf(float x, float y) {
    __nv_bfloat162 t = __floats2bfloat162_rn(x, y);
    return *reinterpret_cast<uint32_t*>(&t);
}
__device__ __forceinline__ void st_bf2(__nv_bfloat16* p, float x, float y) {
    __nv_bfloat162 t = __floats2bfloat162_rn(x, y);
    *reinterpret_cast<__nv_bfloat162*>(p) = t;
}

constexpr int PA = 136;

// =====================================================================
// K0: weight transpose + bf16 convert
// =====================================================================
__global__ void kprep(const float* __restrict__ qkvw, const float* __restrict__ pw,
                      const float* __restrict__ w1,   const float* __restrict__ w2)
{
    int i = blockIdx.x * 256 + threadIdx.x;
    if (i < 49152) { int n = i >> 7, k = i & 127; g_wqkvT[n * 128 + k] = __float2bfloat16(qkvw[k * 384 + n]); return; }
    i -= 49152;
    if (i < 16384) { int n = i >> 7, k = i & 127; g_wpT[n * 128 + k] = __float2bfloat16(pw[k * 128 + n]); return; }
    i -= 16384;
    if (i < 65536) { int n = i >> 7, k = i & 127; g_w1T[n * 128 + k] = __float2bfloat16(w1[k * 512 + n]); return; }
    i -= 65536;
    if (i < 65536) { int n = i >> 9, k = i & 511; g_w2T[n * 512 + k] = __float2bfloat16(w2[k * 128 + n]); return; }
}

// =====================================================================
// K1: BN + window gather + qkv GEMM (M=200704, K=128, N=384)
// =====================================================================
__global__ __launch_bounds__(256) void k1_qkv(
    const float* __restrict__ x,
    const float* __restrict__ bng, const float* __restrict__ bnb,
    const float* __restrict__ bnm, const float* __restrict__ bnv,
    const float* __restrict__ bq)
{
    extern __shared__ unsigned char shraw[];
    __nv_bfloat16* As = (__nv_bfloat16*)shraw;        // [128][PA]
    __nv_bfloat16* Bs = As + 128 * PA;                // [64][PA]
    __shared__ float sc[128], sf[128];
    int tid = threadIdx.x;
    if (tid < 128) {
        float s = bng[tid] * rsqrtf(bnv[tid] + 1e-5f);
        sc[tid] = s;
        sf[tid] = bnb[tid] - bnm[tid] * s;
    }
    __syncthreads();

    int r = tid & 127, cs = tid >> 7;
    int R0 = blockIdx.x * 128;
    {
        int b, sp; row_to_bsp(R0 + r, b, sp);
        const float* xp = x + (size_t)b * 128 * SPT + sp + (size_t)cs * 64 * SPT;
        #pragma unroll 8
        for (int j = 0; j < 64; j++) {
            int c = cs * 64 + j;
            As[r * PA + c] = __float2bfloat16(xp[(size_t)j * SPT] * sc[c] + sf[c]);
        }
    }

    int w = tid >> 5, l = tid & 31;
    int mw = (w >> 1) * 32, nw = (w & 1) * 32;
    int kq = (l & 3) * 2;

    // ldmatrix bases
    uint32_t aA = s2u(As) + (((mw + (l & 15)) * PA + (l >> 4) * 8) << 1);
    uint32_t aB = s2u(Bs) + (((nw + (l & 7) + ((l >> 4) << 3)) * PA + ((l >> 3) & 1) * 8) << 1);

    for (int nt = 0; nt < 6; nt++) {
        __syncthreads();
        for (int i = tid; i < 64 * 16; i += 256) {
            int n = i >> 4, seg = i & 15;
            *(uint4*)&Bs[n * PA + seg * 8] = *(const uint4*)&g_wqkvT[(nt * 64 + n) * 128 + seg * 8];
        }
        __syncthreads();
        float acc[2][4][4];
        #pragma unroll
        for (int a = 0; a < 2; a++)
            #pragma unroll
            for (int bb = 0; bb < 4; bb++)
                acc[a][bb][0] = acc[a][bb][1] = acc[a][bb][2] = acc[a][bb][3] = 0.f;

        #pragma unroll
        for (int k0 = 0; k0 < 128; k0 += 16) {
            uint32_t a0[4], a1[4], b0[4], b1[4];
            ldsm4(a0, aA + k0 * 2);
            ldsm4(a1, aA + 16 * PA * 2 + k0 * 2);
            ldsm4(b0, aB + k0 * 2);
            ldsm4(b1, aB + 16 * PA * 2 + k0 * 2);
            mma4(acc[0][0], a0[0], a0[1], a0[2], a0[3], b0[0], b0[1]);
            mma4(acc[0][1], a0[0], a0[1], a0[2], a0[3], b0[2], b0[3]);
            mma4(acc[0][2], a0[0], a0[1], a0[2], a0[3], b1[0], b1[1]);
            mma4(acc[0][3], a0[0], a0[1], a0[2], a0[3], b1[2], b1[3]);
            mma4(acc[1][0], a1[0], a1[1], a1[2], a1[3], b0[0], b0[1]);
            mma4(acc[1][1], a1[0], a1[1], a1[2], a1[3], b0[2], b0[3]);
            mma4(acc[1][2], a1[0], a1[1], a1[2], a1[3], b1[0], b1[1]);
            mma4(acc[1][3], a1[0], a1[1], a1[2], a1[3], b1[2], b1[3]);
        }
        #pragma unroll
        for (int ntb = 0; ntb < 4; ntb++) {
            int cg = nt * 64 + nw + ntb * 8 + kq;
            float bx = bq[cg], by = bq[cg + 1];
            #pragma unroll
            for (int mt = 0; mt < 2; mt++) {
                int r0 = R0 + mw + mt * 16 + (l >> 2);
                st_bf2(&g_qkv[(size_t)r0 * 384 + cg],       acc[mt][ntb][0] + bx, acc[mt][ntb][1] + by);
                st_bf2(&g_qkv[(size_t)(r0 + 8) * 384 + cg], acc[mt][ntb][2] + bx, acc[mt][ntb][3] + by);
            }
        }
    }
}

// =====================================================================
// K2': per-window attention (4 heads) + proj + residual -> y1.
// =====================================================================
constexpr int PQ2 = 40;    // 80 B/row, 16B-aligned for ldmatrix, conflict-free
constexpr int PVT = 216;
constexpr int PO  = 136;
constexpr int OFF_KS = 208 * PQ2;            // 8320
constexpr int OFF_VT = OFF_KS + 208 * PQ2;   // 16640
constexpr int OFF_O  = OFF_VT + 32 * PVT;    // 23552
constexpr int SM2_ELEMS = OFF_O + 208 * PO;  // 51840

__global__ __launch_bounds__(256) void k2_attnproj(
    const float* __restrict__ x, const float* __restrict__ bp)
{
    extern __shared__ unsigned char shraw[];
    __nv_bfloat16* sm = (__nv_bfloat16*)shraw;
    __nv_bfloat16* Qs = sm;
    __nv_bfloat16* Ks = sm + OFF_KS;
    __nv_bfloat16* Vt = sm + OFF_VT;
    __nv_bfloat16* Os = sm + OFF_O;

    int tid = threadIdx.x, l = tid & 31, wid = tid >> 5;
    int win = blockIdx.x;
    int qbase = win * NTOK;
    int kq = (l & 3) * 2;
    const float scale = 0.17677669529663687f;

    for (int i = tid; i < 12 * PO; i += 256) Os[196 * PO + i] = __float2bfloat16(0.f);

    uint32_t aKbase = s2u(Ks) + ((((l & 7) + ((l >> 4) << 3)) * PQ2 + ((l >> 3) & 1) * 8) << 1);
    uint32_t aVbase = s2u(Vt) + ((((l & 7) + ((l >> 4) << 3)) * PVT + ((l >> 3) & 1) * 8) << 1);

    for (int h = 0; h < 4; h++) {
        __syncthreads();
        int coff = h * 32;
        for (int i = tid; i < 208 * 32; i += 256) {
            int n = i >> 5, d = i & 31;
            __nv_bfloat16 qv, kv, vv;
            if (n < NTOK) {
                const __nv_bfloat16* p = &g_qkv[(size_t)(qbase + n) * 384 + coff + d];
                qv = p[0]; kv = p[128]; vv = p[256];
            } else {
                qv = __float2bfloat16(0.f); kv = qv; vv = qv;
            }
            Qs[n * PQ2 + d] = qv;
            Ks[n * PQ2 + d] = kv;
            Vt[d * PVT + n] = vv;
        }
        __syncthreads();

        for (int u = wid; u < 13; u += 8) {
            int m0 = u * 16;
            float S[26][4];
            #pragma unroll
            for (int t = 0; t < 26; t++) S[t][0] = S[t][1] = S[t][2] = S[t][3] = 0.f;

            uint32_t aQ = s2u(Qs) + (((m0 + (l & 15)) * PQ2 + (l >> 4) * 8) << 1);
            #pragma unroll
            for (int k0 = 0; k0 < 32; k0 += 16) {
                uint32_t aq[4];
                ldsm4(aq, aQ + k0 * 2);
                #pragma unroll
                for (int p = 0; p < 13; p++) {
                    uint32_t bk[4];
                    ldsm4(bk, aKbase + (p * 16 * PQ2 + k0) * 2);
                    mma4(S[2 * p],     aq[0], aq[1], aq[2], aq[3], bk[0], bk[1]);
                    mma4(S[2 * p + 1], aq[0], aq[1], aq[2], aq[3], bk[2], bk[3]);
                }
            }

            float mx0 = -1e30f, mx1 = -1e30f;
            #pragma unroll
            for (int t = 0; t < 26; t++) {
                int c = t * 8 + kq;
                if (c < NTOK)     { mx0 = fmaxf(mx0, S[t][0]); mx1 = fmaxf(mx1, S[t][2]); }
                if (c + 1 < NTOK) { mx0 = fmaxf(mx0, S[t][1]); mx1 = fmaxf(mx1, S[t][3]); }
            }
            mx0 = fmaxf(mx0, __shfl_xor_sync(0xffffffffu, mx0, 1));
            mx0 = fmaxf(mx0, __shfl_xor_sync(0xffffffffu, mx0, 2));
            mx1 = fmaxf(mx1, __shfl_xor_sync(0xffffffffu, mx1, 1));
            mx1 = fmaxf(mx1, __shfl_xor_sync(0xffffffffu, mx1, 2));

            float s0 = 0.f, s1 = 0.f;
            #pragma unroll
            for (int t = 0; t < 26; t++) {
                int c = t * 8 + kq;
                if (c < NTOK)     { S[t][0] = __expf(scale * (S[t][0] - mx0)); s0 += S[t][0];
                                    S[t][2] = __expf(scale * (S[t][2] - mx1)); s1 += S[t][2]; }
                else              { S[t][0] = 0.f; S[t][2] = 0.f; }
                if (c + 1 < NTOK) { S[t][1] = __expf(scale * (S[t][1] - mx0)); s0 += S[t][1];
                                    S[t][3] = __expf(scale * (S[t][3] - mx1)); s1 += S[t][3]; }
                else              { S[t][1] = 0.f; S[t][3] = 0.f; }
            }
            s0 += __shfl_xor_sync(0xffffffffu, s0, 1);
            s0 += __shfl_xor_sync(0xffffffffu, s0, 2);
            s1 += __shfl_xor_sync(0xffffffffu, s1, 1);
            s1 += __shfl_xor_sync(0xffffffffu, s1, 2);
            float i0 = 1.f / s0, i1 = 1.f / s1;
            #pragma unroll
            for (int t = 0; t < 26; t++) {
                S[t][0] *= i0; S[t][1] *= i0; S[t][2] *= i1; S[t][3] *= i1;
            }

            float O[4][4];
            #pragma unroll
            for (int nt = 0; nt < 4; nt++) O[nt][0] = O[nt][1] = O[nt][2] = O[nt][3] = 0.f;
            #pragma unroll
            for (int kt = 0; kt < 13; kt++) {
                uint32_t pa0 = packbf(S[2 * kt][0],     S[2 * kt][1]);
                uint32_t pa1 = packbf(S[2 * kt][2],     S[2 * kt][3]);
                uint32_t pa2 = packbf(S[2 * kt + 1][0], S[2 * kt + 1][1]);
                uint32_t pa3 = packbf(S[2 * kt + 1][2], S[2 * kt + 1][3]);
                #pragma unroll
                for (int p = 0; p < 2; p++) {
                    uint32_t bv[4];
                    ldsm4(bv, aVbase + (p * 16 * PVT + kt * 16) * 2);
                    mma4(O[2 * p],     pa0, pa1, pa2, pa3, bv[0], bv[1]);
                    mma4(O[2 * p + 1], pa0, pa1, pa2, pa3, bv[2], bv[3]);
                }
            }

            int qr0 = m0 + (l >> 2), qr1 = qr0 + 8;
            #pragma unroll
            for (int nt = 0; nt < 4; nt++) {
                int cd = coff + nt * 8 + kq;
                if (qr0 < NTOK) st_bf2(&Os[qr0 * PO + cd], O[nt][0], O[nt][1]);
                if (qr1 < NTOK) st_bf2(&Os[qr1 * PO + cd], O[nt][2], O[nt][3]);
            }
        }
    }

    // ---- proj phase ----
    __syncthreads();
    __nv_bfloat16* Bs = sm;
    for (int i = tid; i < 128 * 16; i += 256) {
        int n = i >> 4, seg = i & 15;
        *(uint4*)&Bs[n * PO + seg * 8] = *(const uint4*)&g_wpT[n * 128 + seg * 8];
    }
    __syncthreads();

    uint32_t aBp = s2u(Bs) + ((((l & 7) + ((l >> 4) << 3)) * PO + ((l >> 3) & 1) * 8) << 1);

    for (int u = wid; u < 13; u += 8) {
        int m0 = u * 16;
        float acc[16][4];
        #pragma unroll
        for (int t = 0; t < 16; t++) acc[t][0] = acc[t][1] = acc[t][2] = acc[t][3] = 0.f;
        uint32_t aO = s2u(Os) + (((m0 + (l & 15)) * PO + (l >> 4) * 8) << 1);
        #pragma unroll
        for (int k0 = 0; k0 < 128; k0 += 16) {
            uint32_t ao[4];
            ldsm4(ao, aO + k0 * 2);
            #pragma unroll
            for (int p = 0; p < 8; p++) {
                uint32_t bb[4];
                ldsm4(bb, aBp + (p * 16 * PO + k0) * 2);
                mma4(acc[2 * p],     ao[0], ao[1], ao[2], ao[3], bb[0], bb[1]);
                mma4(acc[2 * p + 1], ao[0], ao[1], ao[2], ao[3], bb[2], bb[3]);
            }
        }
        #pragma unroll
        for (int half = 0; half < 2; half++) {
            int row = m0 + (l >> 2) + half * 8;
            if (row < NTOK) {
                int b, sp; row_to_bsp(qbase + row, b, sp);
                size_t xb = (size_t)b * 128 * SPT + sp;
                size_t tok = (size_t)b * SPT + sp;
                #pragma unroll
                for (int ntb = 0; ntb < 16; ntb++) {
                    int cg = ntb * 8 + kq;
                    float2 o;
                    o.x = acc[ntb][half * 2 + 0] + bp[cg]     + x[xb + (size_t)cg * SPT];
                    o.y = acc[ntb][half * 2 + 1] + bp[cg + 1] + x[xb + (size_t)(cg + 1) * SPT];
                    *(float2*)&g_y1[tok * 128 + cg] = o;
                }
            }
        }
    }
}

// =====================================================================
// K4: fused LN + fc1 + GELU + fc2 + residual + transposed output.
// =====================================================================
constexpr int OFF_H4 = 128 * PA;
constexpr int OFF_B4 = 2 * 128 * PA;
constexpr int SM4_ELEMS = 3 * 128 * PA;

__global__ __launch_bounds__(256) void k4_ffn(
    const float* __restrict__ lng, const float* __restrict__ lnb,
    const float* __restrict__ b1,  const float* __restrict__ b2,
    float* __restrict__ out)
{
    extern __shared__ unsigned char shraw[];
    __nv_bfloat16* As = (__nv_bfloat16*)shraw;
    __nv_bfloat16* H  = As + OFF_H4;
    __nv_bfloat16* Bs = As + OFF_B4;
    int tid = threadIdx.x, l = tid & 31, w = tid >> 5;
    int R0 = blockIdx.x * 128;

    // LN -> As (bf16)
    {
        int row = tid >> 1, seg = tid & 1;
        const float* src = &g_y1[(size_t)(R0 + row) * 128 + seg * 64];
        float s1 = 0.f, s2 = 0.f;
        #pragma unroll
        for (int j = 0; j < 64; j += 4) {
            float4 t = *(const float4*)&src[j];
            s1 += t.x + t.y + t.z + t.w;
            s2 += t.x * t.x + t.y * t.y + t.z * t.z + t.w * t.w;
        }
        s1 += __shfl_xor_sync(0xffffffffu, s1, 1);
        s2 += __shfl_xor_sync(0xffffffffu, s2, 1);
        float mean = s1 * (1.f / 128.f);
        float var  = s2 * (1.f / 128.f) - mean * mean;
        float rstd = rsqrtf(var + 1e-5f);
        #pragma unroll
        for (int j = 0; j < 64; j += 2) {
            int c = seg * 64 + j;
            float v0 = (src[j]     - mean) * rstd * lng[c]     + lnb[c];
            float v1 = (src[j + 1] - mean) * rstd * lng[c + 1] + lnb[c + 1];
            *(uint32_t*)&As[row * PA + c] = packbf(v0, v1);
        }
    }

    int mw = (w >> 1) * 32, nw = (w & 1) * 32;
    int kq = (l & 3) * 2;

    uint32_t aA4 = s2u(As) + (((mw + (l & 15)) * PA + (l >> 4) * 8) << 1);
    uint32_t aH4 = s2u(H)  + (((mw + (l & 15)) * PA + (l >> 4) * 8) << 1);
    uint32_t bB4 = s2u(Bs) + ((((l & 7) + ((l >> 4) << 3)) * PA + ((l >> 3) & 1) * 8) << 1);

    float acc2[2][2][4][4];
    #pragma unroll
    for (int a = 0; a < 2; a++)
        #pragma unroll
        for (int t = 0; t < 2; t++)
            #pragma unroll
            for (int bb = 0; bb < 4; bb++)
                acc2[a][t][bb][0] = acc2[a][t][bb][1] = acc2[a][t][bb][2] = acc2[a][t][bb][3] = 0.f;

    for (int kc = 0; kc < 4; kc++) {
        __syncthreads();
        for (int i = tid; i < 128 * 16; i += 256) {
            int n = i >> 4, seg = i & 15;
            *(uint4*)&Bs[n * PA + seg * 8] = *(const uint4*)&g_w1T[(size_t)(kc * 128 + n) * 128 + seg * 8];
        }
        __syncthreads();

        // fc1 + GELU -> H
        #pragma unroll
        for (int nt = 0; nt < 2; nt++) {
            float acc[2][4][4];
            #pragma unroll
            for (int a = 0; a < 2; a++)
                #pragma unroll
                for (int bb = 0; bb < 4; bb++)
                    acc[a][bb][0] = acc[a][bb][1] = acc[a][bb][2] = acc[a][bb][3] = 0.f;

            #pragma unroll
            for (int k0 = 0; k0 < 128; k0 += 16) {
                uint32_t a0[4], a1[4], b0[4], b1[4];
                ldsm4(a0, aA4 + k0 * 2);
                ldsm4(a1, aA4 + 16 * PA * 2 + k0 * 2);
                ldsm4(b0, bB4 + ((nt * 64 + nw) * PA + k0) * 2);
                ldsm4(b1, bB4 + ((nt * 64 + nw + 16) * PA + k0) * 2);
                mma4(acc[0][0], a0[0], a0[1], a0[2], a0[3], b0[0], b0[1]);
                mma4(acc[0][1], a0[0], a0[1], a0[2], a0[3], b0[2], b0[3]);
                mma4(acc[0][2], a0[0], a0[1], a0[2], a0[3], b1[0], b1[1]);
                mma4(acc[0][3], a0[0], a0[1], a0[2], a0[3], b1[2], b1[3]);
                mma4(acc[1][0], a1[0], a1[1], a1[2], a1[3], b0[0], b0[1]);
                mma4(acc[1][1], a1[0], a1[1], a1[2], a1[3], b0[2], b0[3]);
                mma4(acc[1][2], a1[0], a1[1], a1[2], a1[3], b1[0], b1[1]);
                mma4(acc[1][3], a1[0], a1[1], a1[2], a1[3], b1[2], b1[3]);
            }
            #pragma unroll
            for (int ntb = 0; ntb < 4; ntb++) {
                int cl = nt * 64 + nw + ntb * 8 + kq;
                float bx = b1[kc * 128 + cl], by = b1[kc * 128 + cl + 1];
                #pragma unroll
                for (int mt = 0; mt < 2; mt++) {
                    #pragma unroll
                    for (int half = 0; half < 2; half++) {
                        int row = mw + mt * 16 + (l >> 2) + half * 8;
                        float h0 = acc[mt][ntb][half * 2 + 0] + bx;
                        float h1 = acc[mt][ntb][half * 2 + 1] + by;
                        float g0 = 0.5f * h0 * (1.f + erff(h0 * 0.70710678118654752f));
                        float g1 = 0.5f * h1 * (1.f + erff(h1 * 0.70710678118654752f));
                        st_bf2(&H[row * PA + cl], g0, g1);
                    }
                }
            }
        }
        __syncthreads();
        for (int i = tid; i < 128 * 16; i += 256) {
            int n = i >> 4, seg = i & 15;
            *(uint4*)&Bs[n * PA + seg * 8] = *(const uint4*)&g_w2T[(size_t)n * 512 + kc * 128 + seg * 8];
        }
        __syncthreads();
        // fc2 accumulate
        #pragma unroll
        for (int k0 = 0; k0 < 128; k0 += 16) {
            uint32_t a0[4], a1[4];
            ldsm4(a0, aH4 + k0 * 2);
            ldsm4(a1, aH4 + 16 * PA * 2 + k0 * 2);
            #pragma unroll
            for (int t = 0; t < 2; t++) {
                uint32_t b0[4], b1[4];
                ldsm4(b0, bB4 + ((t * 64 + nw) * PA + k0) * 2);
                ldsm4(b1, bB4 + ((t * 64 + nw + 16) * PA + k0) * 2);
                mma4(acc2[0][t][0], a0[0], a0[1], a0[2], a0[3], b0[0], b0[1]);
                mma4(acc2[0][t][1], a0[0], a0[1], a0[2], a0[3], b0[2], b0[3]);
                mma4(acc2[0][t][2], a0[0], a0[1], a0[2], a0[3], b1[0], b1[1]);
                mma4(acc2[0][t][3], a0[0], a0[1], a0[2], a0[3], b1[2], b1[3]);
                mma4(acc2[1][t][0], a1[0], a1[1], a1[2], a1[3], b0[0], b0[1]);
                mma4(acc2[1][t][1], a1[0], a1[1], a1[2], a1[3], b0[2], b0[3]);
                mma4(acc2[1][t][2], a1[0], a1[1], a1[2], a1[3], b1[0], b1[1]);
                mma4(acc2[1][t][3], a1[0], a1[1], a1[2], a1[3], b1[2], b1[3]);
            }
        }
    }

    __syncthreads();
    float* Cs = (float*)shraw;   // [128][133]
    #pragma unroll
    for (int mt = 0; mt < 2; mt++) {
        #pragma unroll
        for (int half = 0; half < 2; half++) {
            int row = mw + mt * 16 + (l >> 2) + half * 8;
            #pragma unroll
            for (int t = 0; t < 2; t++) {
                #pragma unroll
                for (int ntb = 0; ntb < 4; ntb++) {
                    int c = t * 64 + nw + ntb * 8 + kq;
                    float2 yv = *(const float2*)&g_y1[(size_t)(R0 + row) * 128 + c];
                    Cs[row * 133 + c]     = acc2[mt][t][ntb][half * 2 + 0] + b2[c]     + yv.x;
                    Cs[row * 133 + c + 1] = acc2[mt][t][ntb][half * 2 + 1] + b2[c + 1] + yv.y;
                }
            }
        }
    }
    __syncthreads();

    int rl = tid & 127, cg = tid >> 7;
    int R = R0 + rl;
    int b = R / SPT, sp = R - b * SPT;
    size_t obase = (size_t)b * 128 * SPT + sp;
    #pragma unroll 8
    for (int j = 0; j < 64; j++) {
        int col = cg * 64 + j;
        out[obase + (size_t)col * SPT] = Cs[rl * 133 + col];
    }
}

// =====================================================================
extern "C" void kernel_launch(void* const* d_in, const int* in_sizes, int n_in,
                              void* d_out, int out_size)
{
    const float* x    = (const float*)d_in[0];
    const float* bng  = (const float*)d_in[1];
    const float* bnb  = (const float*)d_in[2];
    const float* bnm  = (const float*)d_in[3];
    const float* bnv  = (const float*)d_in[4];
    const float* qkvw = (const float*)d_in[5];
    const float* qkvb = (const float*)d_in[6];
    const float* pw   = (const float*)d_in[7];
    const float* pb   = (const float*)d_in[8];
    const float* lng  = (const float*)d_in[9];
    const float* lnb  = (const float*)d_in[10];
    const float* w1   = (const float*)d_in[11];
    const float* b1   = (const float*)d_in[12];
    const float* w2   = (const float*)d_in[13];
    const float* b2   = (const float*)d_in[14];
    float* out = (float*)d_out;

    const int smem1 = (128 * PA + 64 * PA) * 2;
    const int smem2 = SM2_ELEMS * 2;     // 103680
    const int smem4 = SM4_ELEMS * 2;

    cudaFuncSetAttribute(k1_qkv,      cudaFuncAttributeMaxDynamicSharedMemorySize, smem1);
    cudaFuncSetAttribute(k2_attnproj, cudaFuncAttributeMaxDynamicSharedMemorySize, smem2);
    cudaFuncSetAttribute(k4_ffn,      cudaFuncAttributeMaxDynamicSharedMemorySize, smem4);

    kprep       <<<768, 256>>>(qkvw, pw, w1, w2);
    k1_qkv      <<<MTOK / 128, 256, smem1>>>(x, bng, bnb, bnm, bnv, qkvb);
    k2_attnproj <<<NWIN, 256, smem2>>>(x, pb);
    k4_ffn      <<<MTOK / 128, 256, smem4>>>(lng, lnb, b1, b2, out);
}